// round 3
// baseline (speedup 1.0000x reference)
#include <cuda_runtime.h>

#define MAXN 100000
#define MAXE 3200000
#define IN_DIM 512
#define OUT_DIM 256

// ---------------- scratch (static __device__, no runtime allocation) ----------------
__device__ float g_support[(size_t)MAXN * OUT_DIM];   // tanh(x@W), 102.4 MB
__device__ int   g_count[MAXN];
__device__ int   g_rowstart[MAXN + 1];
__device__ int   g_cursor[MAXN];
__device__ int   g_ecol[MAXE];
__device__ float g_eval[MAXE];

// ---------------- GEMM (fp32, packed f32x2 FFMA2) + tanh ----------------
#define BM 128
#define BN 64
#define BK 16

__device__ __forceinline__ void fma2(unsigned long long &d,
                                     unsigned long long a,
                                     unsigned long long b) {
    asm("fma.rn.f32x2 %0, %1, %2, %0;" : "+l"(d) : "l"(a), "l"(b));
}

union U64F2 { unsigned long long u; float2 f; };

__global__ __launch_bounds__(256) void gemm_tanh_kernel(
    const float* __restrict__ x, const float* __restrict__ w,
    const int* __restrict__ act_ptr, int M)
{
    // A tile stored as duplicated pairs (v,v) so inner loop needs no pack MOVs
    __shared__ __align__(16) float2 As[BK][BM];   // 16 KB
    __shared__ __align__(16) float  Bs[BK][BN];   // 4 KB

    const int tid = threadIdx.x;
    const int ty = tid >> 4;      // 0..15 : row group (8 rows each)
    const int tx = tid & 15;      // 0..15 : col group (4 cols each)
    const int bm = blockIdx.x * BM;
    const int bn = blockIdx.y * BN;

    unsigned long long acc[8][2];
    #pragma unroll
    for (int r = 0; r < 8; r++) { acc[r][0] = 0ull; acc[r][1] = 0ull; }

    for (int kk = 0; kk < IN_DIM; kk += BK) {
        // load A tile: 128x16 floats = 512 float4, 2 per thread, transposed+duplicated
        #pragma unroll
        for (int i = 0; i < 2; i++) {
            int li = tid + i * 256;
            int arow = li >> 2, acol = li & 3;
            int grow = bm + arow;
            float4 v = make_float4(0.f, 0.f, 0.f, 0.f);
            if (grow < M)
                v = *(const float4*)(x + (size_t)grow * IN_DIM + kk + acol * 4);
            As[acol * 4 + 0][arow] = make_float2(v.x, v.x);
            As[acol * 4 + 1][arow] = make_float2(v.y, v.y);
            As[acol * 4 + 2][arow] = make_float2(v.z, v.z);
            As[acol * 4 + 3][arow] = make_float2(v.w, v.w);
        }
        // load B tile: 16x64 floats = 256 float4, 1 per thread
        {
            int brow = tid >> 4;
            int bc = (tid & 15) * 4;
            *(float4*)&Bs[brow][bc] =
                *(const float4*)(w + (size_t)(kk + brow) * OUT_DIM + bn + bc);
        }
        __syncthreads();

        #pragma unroll
        for (int k = 0; k < BK; k++) {
            ulonglong2 b = *(ulonglong2*)&Bs[k][tx * 4];       // cols (0,1) and (2,3)
            const ulonglong2* ap = (const ulonglong2*)&As[k][ty * 8];
            #pragma unroll
            for (int rr = 0; rr < 4; rr++) {
                ulonglong2 a2 = ap[rr];                        // rows 2rr, 2rr+1 (dup pairs)
                fma2(acc[rr * 2 + 0][0], a2.x, b.x);
                fma2(acc[rr * 2 + 0][1], a2.x, b.y);
                fma2(acc[rr * 2 + 1][0], a2.y, b.x);
                fma2(acc[rr * 2 + 1][1], a2.y, b.y);
            }
        }
        __syncthreads();
    }

    int act = act_ptr ? act_ptr[0] : 1;
    #pragma unroll
    for (int r = 0; r < 8; r++) {
        int row = bm + ty * 8 + r;
        if (row < M) {
            U64F2 u0, u1; u0.u = acc[r][0]; u1.u = acc[r][1];
            float4 o = make_float4(u0.f.x, u0.f.y, u1.f.x, u1.f.y);
            if (act) {
                o.x = tanhf(o.x); o.y = tanhf(o.y);
                o.z = tanhf(o.z); o.w = tanhf(o.w);
            }
            *(float4*)&g_support[(size_t)row * OUT_DIM + bn + tx * 4] = o;
        }
    }
}

// ---------------- CSR build ----------------
__global__ void zero_counts(int N) {
    int i = blockIdx.x * blockDim.x + threadIdx.x;
    if (i < N) g_count[i] = 0;
}

__global__ void hist_kernel(const int* __restrict__ rows, int E) {
    int i = blockIdx.x * blockDim.x + threadIdx.x;
    if (i < E) atomicAdd(&g_count[rows[i]], 1);
}

__global__ __launch_bounds__(1024) void scan_kernel(int N, int E) {
    __shared__ int warpsums[32];
    __shared__ int s_carry;
    int tid = threadIdx.x, lane = tid & 31, wid = tid >> 5;
    if (tid == 0) s_carry = 0;
    __syncthreads();
    for (int base = 0; base < N; base += 1024) {
        int i = base + tid;
        int v = (i < N) ? g_count[i] : 0;
        int xv = v;
        #pragma unroll
        for (int o = 1; o < 32; o <<= 1) {
            int t = __shfl_up_sync(0xFFFFFFFFu, xv, o);
            if (lane >= o) xv += t;
        }
        if (lane == 31) warpsums[wid] = xv;
        __syncthreads();
        if (wid == 0) {
            int wv = warpsums[lane];
            int y = wv;
            #pragma unroll
            for (int o = 1; o < 32; o <<= 1) {
                int t = __shfl_up_sync(0xFFFFFFFFu, y, o);
                if (lane >= o) y += t;
            }
            warpsums[lane] = y - wv;   // exclusive warp offsets
        }
        __syncthreads();
        int excl = s_carry + warpsums[wid] + xv - v;
        if (i < N) { g_rowstart[i] = excl; g_cursor[i] = excl; }
        __syncthreads();
        if (tid == 1023) s_carry = excl + v;   // running total through this chunk
        __syncthreads();
    }
    if (tid == 0) g_rowstart[N] = E;
}

__global__ void scatter_kernel(const int* __restrict__ rows,
                               const int* __restrict__ cols,
                               const float* __restrict__ vals, int E) {
    int i = blockIdx.x * blockDim.x + threadIdx.x;
    if (i < E) {
        int r = rows[i];
        int p = atomicAdd(&g_cursor[r], 1);
        g_ecol[p] = cols[i];
        g_eval[p] = vals[i];
    }
}

// ---------------- SpMM: one warp per row, register accumulation, no float atomics ----------------
__global__ __launch_bounds__(256) void spmm_kernel(float* __restrict__ out, int N) {
    int wrow = (blockIdx.x * blockDim.x + threadIdx.x) >> 5;
    int lane = threadIdx.x & 31;
    if (wrow >= N) return;
    int s = g_rowstart[wrow];
    int e = g_rowstart[wrow + 1];
    float a0 = 0.f, a1 = 0.f, a2 = 0.f, a3 = 0.f;
    float a4 = 0.f, a5 = 0.f, a6 = 0.f, a7 = 0.f;
    for (int i = s; i < e; i++) {
        int   c = g_ecol[i];
        float v = g_eval[i];
        const float4* sp = (const float4*)(g_support + (size_t)c * OUT_DIM);
        float4 p0 = sp[lane];
        float4 p1 = sp[lane + 32];
        a0 += v * p0.x; a1 += v * p0.y; a2 += v * p0.z; a3 += v * p0.w;
        a4 += v * p1.x; a5 += v * p1.y; a6 += v * p1.z; a7 += v * p1.w;
    }
    float4* op = (float4*)(out + (size_t)wrow * OUT_DIM);
    op[lane]      = make_float4(a0, a1, a2, a3);
    op[lane + 32] = make_float4(a4, a5, a6, a7);
}

// ---------------- launch ----------------
extern "C" void kernel_launch(void* const* d_in, const int* in_sizes, int n_in,
                              void* d_out, int out_size) {
    const float* x    = (const float*)d_in[0];
    const float* w    = (const float*)d_in[1];
    const int*   erow = (const int*)d_in[2];
    const int*   ecol = (const int*)d_in[3];
    const float* eval = (const float*)d_in[4];
    const int*   act  = (n_in > 5) ? (const int*)d_in[5] : nullptr;

    int M = in_sizes[0] / IN_DIM;   // 100000
    int E = in_sizes[2];            // 3200000
    float* out = (float*)d_out;

    dim3 ggrid((M + BM - 1) / BM, OUT_DIM / BN);
    gemm_tanh_kernel<<<ggrid, 256>>>(x, w, act, M);

    zero_counts<<<(M + 255) / 256, 256>>>(M);
    hist_kernel<<<(E + 255) / 256, 256>>>(erow, E);
    scan_kernel<<<1, 1024>>>(M, E);
    scatter_kernel<<<(E + 255) / 256, 256>>>(erow, ecol, eval, E);

    long long spmm_threads = (long long)M * 32;
    spmm_kernel<<<(unsigned)((spmm_threads + 255) / 256), 256>>>(out, M);
}

// round 7
// speedup vs baseline: 1.9621x; 1.9621x over previous
#include <cuda_runtime.h>
#include <cuda_fp16.h>
#include <cuda_bf16.h>
#include <cstdint>

#define MAXN 100000
#define MAXE 3200000
#define IN_DIM 512
#define OUT_DIM 256

// ---------------- scratch (static __device__, no runtime allocation) ----------------
__device__ __half          g_support_h[(size_t)MAXN * OUT_DIM];   // tanh(x@W) in fp16, 51.2 MB
__device__ __nv_bfloat16   g_whiT[(size_t)OUT_DIM * IN_DIM];      // W^T hi  [256][512]
__device__ __nv_bfloat16   g_wloT[(size_t)OUT_DIM * IN_DIM];      // W^T lo
__device__ int   g_count[MAXN];
__device__ int   g_rowstart[MAXN + 1];
__device__ int   g_cursor[MAXN];
__device__ int   g_ecol[MAXE];
__device__ float g_eval[MAXE];
__device__ int   g_blocksum[128];
__device__ int   g_blockoff[128];

// ======================= helpers =======================
__device__ __forceinline__ uint32_t smem_u32(const void* p) {
    uint32_t a;
    asm("{ .reg .u64 t; cvta.to.shared.u64 t, %1; cvt.u32.u64 %0, t; }" : "=r"(a) : "l"(p));
    return a;
}

__device__ __forceinline__ void ldmx4(uint32_t& r0, uint32_t& r1, uint32_t& r2, uint32_t& r3,
                                      uint32_t addr) {
    asm volatile("ldmatrix.sync.aligned.m8n8.x4.shared.b16 {%0,%1,%2,%3}, [%4];"
                 : "=r"(r0), "=r"(r1), "=r"(r2), "=r"(r3) : "r"(addr));
}

__device__ __forceinline__ void mma_bf16(float* c, const uint32_t* a, const uint32_t* b) {
    asm volatile(
        "mma.sync.aligned.m16n8k16.row.col.f32.bf16.bf16.f32 "
        "{%0,%1,%2,%3}, {%4,%5,%6,%7}, {%8,%9}, {%0,%1,%2,%3};"
        : "+f"(c[0]), "+f"(c[1]), "+f"(c[2]), "+f"(c[3])
        : "r"(a[0]), "r"(a[1]), "r"(a[2]), "r"(a[3]), "r"(b[0]), "r"(b[1]));
}

// ======================= W transpose + bf16 hi/lo split =======================
__global__ void convw_kernel(const float* __restrict__ w) {
    int idx = blockIdx.x * blockDim.x + threadIdx.x;   // over 512*256
    if (idx >= IN_DIM * OUT_DIM) return;
    int k = idx / OUT_DIM, n = idx % OUT_DIM;
    float f = w[idx];
    __nv_bfloat16 hi = __float2bfloat16_rn(f);
    float lof = f - __bfloat162float(hi);
    __nv_bfloat16 lo = __float2bfloat16_rn(lof);
    g_whiT[(size_t)n * IN_DIM + k] = hi;
    g_wloT[(size_t)n * IN_DIM + k] = lo;
}

// ======================= split-bf16 HMMA GEMM + tanh -> fp16 =======================
// CTA tile 128(M) x 128(N), BK=32, 8 warps in 4x2 (warp tile 32x64).
// SMEM rows padded to 40 bf16 (80 B, 16B-aligned, conflict-free ldmatrix).
#define GBK 32
#define GSTRIDE 40

__global__ __launch_bounds__(256, 1)
void gemm_mma_kernel(const float* __restrict__ x, const int* __restrict__ act_ptr, int M)
{
    __shared__ __align__(16) __nv_bfloat16 sAhi[128 * GSTRIDE];
    __shared__ __align__(16) __nv_bfloat16 sAlo[128 * GSTRIDE];
    __shared__ __align__(16) __nv_bfloat16 sBhi[128 * GSTRIDE];
    __shared__ __align__(16) __nv_bfloat16 sBlo[128 * GSTRIDE];

    const int tid = threadIdx.x;
    const int lane = tid & 31, wid = tid >> 5;
    const int bm = blockIdx.x * 128;
    const int bn = blockIdx.y * 128;
    const int wm = (wid & 3) * 32;    // warp M offset within CTA tile
    const int wn = (wid >> 2) * 64;   // warp N offset

    const uint32_t sAhi_b = smem_u32(sAhi);
    const uint32_t sAlo_b = smem_u32(sAlo);
    const uint32_t sBhi_b = smem_u32(sBhi);
    const uint32_t sBlo_b = smem_u32(sBlo);

    float acc[2][8][4];
    #pragma unroll
    for (int i = 0; i < 2; i++)
        #pragma unroll
        for (int j = 0; j < 8; j++)
            #pragma unroll
            for (int q = 0; q < 4; q++) acc[i][j][q] = 0.f;

    // precomputed ldmatrix lane addresses (element offsets; *2 for bytes)
    const int a_row = (lane & 15), a_koff = (lane >> 4) * 8;
    const int b_row = (lane & 7) + ((lane >> 4) & 1) * 8, b_koff = ((lane >> 3) & 1) * 8;

    for (int chunk = 0; chunk < IN_DIM / GBK; chunk++) {
        const int kk = chunk * GBK;

        // ---- A tile: 128 rows x 32 fp32 -> bf16 hi/lo. 1024 float4, 4/thread ----
        #pragma unroll
        for (int it = 0; it < 4; it++) {
            int i = tid + it * 256;
            int row = i >> 3, f4 = i & 7;
            float4 v = make_float4(0.f, 0.f, 0.f, 0.f);
            int grow = bm + row;
            if (grow < M)
                v = *(const float4*)(x + (size_t)grow * IN_DIM + kk + f4 * 4);
            __nv_bfloat16 hx = __float2bfloat16_rn(v.x), hy = __float2bfloat16_rn(v.y);
            __nv_bfloat16 hz = __float2bfloat16_rn(v.z), hw = __float2bfloat16_rn(v.w);
            __nv_bfloat16 lx = __float2bfloat16_rn(v.x - __bfloat162float(hx));
            __nv_bfloat16 ly = __float2bfloat16_rn(v.y - __bfloat162float(hy));
            __nv_bfloat16 lz = __float2bfloat16_rn(v.z - __bfloat162float(hz));
            __nv_bfloat16 lw = __float2bfloat16_rn(v.w - __bfloat162float(hw));
            __nv_bfloat162 h01(hx, hy), h23(hz, hw), l01(lx, ly), l23(lz, lw);
            int off = row * GSTRIDE + f4 * 4;
            *(uint2*)&sAhi[off] = make_uint2(*(uint32_t*)&h01, *(uint32_t*)&h23);
            *(uint2*)&sAlo[off] = make_uint2(*(uint32_t*)&l01, *(uint32_t*)&l23);
        }
        // ---- B tiles: 128 n-rows x 32 k bf16 (hi & lo). 512 uint4 each, 2/thread ----
        #pragma unroll
        for (int it = 0; it < 2; it++) {
            int i = tid + it * 256;
            int row = i >> 2, seg = i & 3;
            size_t gsrc = (size_t)(bn + row) * IN_DIM + kk + seg * 8;
            int off = row * GSTRIDE + seg * 8;
            *(uint4*)&sBhi[off] = *(const uint4*)(g_whiT + gsrc);
            *(uint4*)&sBlo[off] = *(const uint4*)(g_wloT + gsrc);
        }
        __syncthreads();

        #pragma unroll
        for (int ks = 0; ks < 2; ks++) {
            const int k0 = ks * 16;
            uint32_t ah[2][4], al[2][4];
            #pragma unroll
            for (int mt = 0; mt < 2; mt++) {
                uint32_t eoff = (uint32_t)((wm + mt * 16 + a_row) * GSTRIDE + k0 + a_koff) * 2u;
                ldmx4(ah[mt][0], ah[mt][1], ah[mt][2], ah[mt][3], sAhi_b + eoff);
                ldmx4(al[mt][0], al[mt][1], al[mt][2], al[mt][3], sAlo_b + eoff);
            }
            #pragma unroll
            for (int nt2 = 0; nt2 < 4; nt2++) {
                uint32_t eoff = (uint32_t)((wn + nt2 * 16 + b_row) * GSTRIDE + k0 + b_koff) * 2u;
                uint32_t bh[4], bl[4];
                ldmx4(bh[0], bh[1], bh[2], bh[3], sBhi_b + eoff);
                ldmx4(bl[0], bl[1], bl[2], bl[3], sBlo_b + eoff);
                #pragma unroll
                for (int mt = 0; mt < 2; mt++) {
                    #pragma unroll
                    for (int j = 0; j < 2; j++) {
                        float* c = acc[mt][nt2 * 2 + j];
                        const uint32_t* bfh = &bh[j * 2];
                        const uint32_t* bfl = &bl[j * 2];
                        mma_bf16(c, ah[mt], bfh);   // hi*hi
                        mma_bf16(c, ah[mt], bfl);   // hi*lo
                        mma_bf16(c, al[mt], bfh);   // lo*hi
                    }
                }
            }
        }
        __syncthreads();
    }

    // ---- epilogue: tanh -> fp16 ----
    const int act = act_ptr ? act_ptr[0] : 1;
    #pragma unroll
    for (int mt = 0; mt < 2; mt++) {
        int r0 = bm + wm + mt * 16 + (lane >> 2);
        #pragma unroll
        for (int nt = 0; nt < 8; nt++) {
            int col = bn + wn + nt * 8 + (lane & 3) * 2;
            float c0 = acc[mt][nt][0], c1 = acc[mt][nt][1];
            float c2 = acc[mt][nt][2], c3 = acc[mt][nt][3];
            if (act) { c0 = tanhf(c0); c1 = tanhf(c1); c2 = tanhf(c2); c3 = tanhf(c3); }
            if (r0 < M)
                *(__half2*)(g_support_h + (size_t)r0 * OUT_DIM + col) = __floats2half2_rn(c0, c1);
            if (r0 + 8 < M)
                *(__half2*)(g_support_h + (size_t)(r0 + 8) * OUT_DIM + col) = __floats2half2_rn(c2, c3);
        }
    }
}

// ======================= CSR build =======================
__global__ void zero_counts(int N) {
    int i = blockIdx.x * blockDim.x + threadIdx.x;
    if (i < N) g_count[i] = 0;
}

__global__ void hist_kernel(const int* __restrict__ rows, int E) {
    int i = blockIdx.x * blockDim.x + threadIdx.x;
    if (i < E) atomicAdd(&g_count[rows[i]], 1);
}

// -- parallel scan, 3 phases, 1024 counts per block --
__global__ __launch_bounds__(1024) void scan_phase1(int N) {
    __shared__ int ws[32];
    int b = blockIdx.x, tid = threadIdx.x, lane = tid & 31, wid = tid >> 5;
    int i = b * 1024 + tid;
    int v = (i < N) ? g_count[i] : 0;
    #pragma unroll
    for (int o = 16; o > 0; o >>= 1) v += __shfl_down_sync(0xFFFFFFFFu, v, o);
    if (lane == 0) ws[wid] = v;
    __syncthreads();
    if (wid == 0) {
        int s = ws[lane];
        #pragma unroll
        for (int o = 16; o > 0; o >>= 1) s += __shfl_down_sync(0xFFFFFFFFu, s, o);
        if (lane == 0) g_blocksum[b] = s;
    }
}

__global__ __launch_bounds__(128) void scan_phase2(int NB) {
    __shared__ int ws[4];
    int tid = threadIdx.x, lane = tid & 31, wid = tid >> 5;
    int v = (tid < NB) ? g_blocksum[tid] : 0;
    int xv = v;
    #pragma unroll
    for (int o = 1; o < 32; o <<= 1) {
        int t = __shfl_up_sync(0xFFFFFFFFu, xv, o);
        if (lane >= o) xv += t;
    }
    if (lane == 31) ws[wid] = xv;
    __syncthreads();
    int carry = 0;
    #pragma unroll
    for (int w = 0; w < 4; w++) { if (w < wid) carry += ws[w]; }
    if (tid < NB) g_blockoff[tid] = carry + xv - v;   // exclusive
}

__global__ __launch_bounds__(1024) void scan_phase3(int N, int E) {
    __shared__ int ws[32];
    int b = blockIdx.x, tid = threadIdx.x, lane = tid & 31, wid = tid >> 5;
    int i = b * 1024 + tid;
    int v = (i < N) ? g_count[i] : 0;
    int xv = v;
    #pragma unroll
    for (int o = 1; o < 32; o <<= 1) {
        int t = __shfl_up_sync(0xFFFFFFFFu, xv, o);
        if (lane >= o) xv += t;
    }
    if (lane == 31) ws[wid] = xv;
    __syncthreads();
    if (wid == 0) {
        int wv = ws[lane];
        int y = wv;
        #pragma unroll
        for (int o = 1; o < 32; o <<= 1) {
            int t = __shfl_up_sync(0xFFFFFFFFu, y, o);
            if (lane >= o) y += t;
        }
        ws[lane] = y - wv;   // exclusive warp offsets
    }
    __syncthreads();
    int off = g_blockoff[b] + ws[wid] + xv - v;   // global exclusive prefix
    if (i < N) { g_rowstart[i] = off; g_cursor[i] = off; }
    if (i == N - 1) g_rowstart[N] = off + v;      // == E
}

__global__ void scatter_kernel(const int* __restrict__ rows,
                               const int* __restrict__ cols,
                               const float* __restrict__ vals, int E) {
    int i = blockIdx.x * blockDim.x + threadIdx.x;
    if (i < E) {
        int r = rows[i];
        int p = atomicAdd(&g_cursor[r], 1);
        g_ecol[p] = cols[i];
        g_eval[p] = vals[i];
    }
}

// ======================= SpMM (fp16 gather, warp per row) =======================
__global__ __launch_bounds__(256) void spmm_kernel(float* __restrict__ out, int N) {
    int wrow = (blockIdx.x * blockDim.x + threadIdx.x) >> 5;
    int lane = threadIdx.x & 31;
    if (wrow >= N) return;
    int s = g_rowstart[wrow];
    int e = g_rowstart[wrow + 1];
    float a0 = 0.f, a1 = 0.f, a2 = 0.f, a3 = 0.f;
    float a4 = 0.f, a5 = 0.f, a6 = 0.f, a7 = 0.f;
    for (int i = s; i < e; i++) {
        int   c = g_ecol[i];
        float v = g_eval[i];
        uint4 q = *(const uint4*)(g_support_h + (size_t)c * OUT_DIM + lane * 8);
        float2 f0 = __half22float2(*(const __half2*)&q.x);
        float2 f1 = __half22float2(*(const __half2*)&q.y);
        float2 f2 = __half22float2(*(const __half2*)&q.z);
        float2 f3 = __half22float2(*(const __half2*)&q.w);
        a0 += v * f0.x; a1 += v * f0.y; a2 += v * f1.x; a3 += v * f1.y;
        a4 += v * f2.x; a5 += v * f2.y; a6 += v * f3.x; a7 += v * f3.y;
    }
    float* op = out + (size_t)wrow * OUT_DIM + lane * 8;
    *(float4*)(op)     = make_float4(a0, a1, a2, a3);
    *(float4*)(op + 4) = make_float4(a4, a5, a6, a7);
}

// ======================= launch =======================
extern "C" void kernel_launch(void* const* d_in, const int* in_sizes, int n_in,
                              void* d_out, int out_size) {
    const float* x    = (const float*)d_in[0];
    const float* w    = (const float*)d_in[1];
    const int*   erow = (const int*)d_in[2];
    const int*   ecol = (const int*)d_in[3];
    const float* eval = (const float*)d_in[4];
    const int*   act  = (n_in > 5) ? (const int*)d_in[5] : nullptr;

    int M = in_sizes[0] / IN_DIM;   // 100000
    int E = in_sizes[2];            // 3200000
    float* out = (float*)d_out;

    convw_kernel<<<(IN_DIM * OUT_DIM + 255) / 256, 256>>>(w);

    dim3 ggrid((M + 127) / 128, OUT_DIM / 128);
    gemm_mma_kernel<<<ggrid, 256>>>(x, act, M);

    zero_counts<<<(M + 255) / 256, 256>>>(M);
    hist_kernel<<<(E + 255) / 256, 256>>>(erow, E);

    int NB = (M + 1023) / 1024;     // 98
    scan_phase1<<<NB, 1024>>>(M);
    scan_phase2<<<1, 128>>>(NB);
    scan_phase3<<<NB, 1024>>>(M, E);

    scatter_kernel<<<(E + 255) / 256, 256>>>(erow, ecol, eval, E);

    long long spmm_threads = (long long)M * 32;
    spmm_kernel<<<(unsigned)((spmm_threads + 255) / 256), 256>>>(out, M);
}

// round 8
// speedup vs baseline: 2.1644x; 1.1031x over previous
#include <cuda_runtime.h>
#include <cuda_fp16.h>
#include <cuda_bf16.h>
#include <cstdint>

#define MAXN 100000
#define MAXE 3200000
#define IN_DIM 512
#define OUT_DIM 256

// ---------------- scratch (static __device__, no runtime allocation) ----------------
__device__ __half          g_support_h[(size_t)MAXN * OUT_DIM];   // tanh(x@W) in fp16, 51.2 MB
__device__ __nv_bfloat16   g_whiT[(size_t)OUT_DIM * IN_DIM];      // W^T hi  [256][512]
__device__ __nv_bfloat16   g_wloT[(size_t)OUT_DIM * IN_DIM];      // W^T lo
__device__ int   g_count[MAXN];
__device__ int   g_rowstart[MAXN + 1];
__device__ int   g_cursor[MAXN];
__device__ int2  g_edge[MAXE];          // packed (col, val-bits)
__device__ int   g_blocksum[128];
__device__ int   g_blockoff[128];

// ---------------- host-side stream/event objects (created at load, before capture) ----------------
static cudaStream_t g_sB;
static cudaEvent_t  g_evFork, g_evJoin;
struct _InitStreams {
    _InitStreams() {
        cudaStreamCreate(&g_sB);
        cudaEventCreateWithFlags(&g_evFork, cudaEventDisableTiming);
        cudaEventCreateWithFlags(&g_evJoin, cudaEventDisableTiming);
    }
};
static _InitStreams g_init_streams;

// ======================= helpers =======================
__device__ __forceinline__ uint32_t smem_u32(const void* p) {
    uint32_t a;
    asm("{ .reg .u64 t; cvta.to.shared.u64 t, %1; cvt.u32.u64 %0, t; }" : "=r"(a) : "l"(p));
    return a;
}

__device__ __forceinline__ void ldmx4(uint32_t& r0, uint32_t& r1, uint32_t& r2, uint32_t& r3,
                                      uint32_t addr) {
    asm volatile("ldmatrix.sync.aligned.m8n8.x4.shared.b16 {%0,%1,%2,%3}, [%4];"
                 : "=r"(r0), "=r"(r1), "=r"(r2), "=r"(r3) : "r"(addr));
}

__device__ __forceinline__ void mma_bf16(float* c, const uint32_t* a, const uint32_t* b) {
    asm volatile(
        "mma.sync.aligned.m16n8k16.row.col.f32.bf16.bf16.f32 "
        "{%0,%1,%2,%3}, {%4,%5,%6,%7}, {%8,%9}, {%0,%1,%2,%3};"
        : "+f"(c[0]), "+f"(c[1]), "+f"(c[2]), "+f"(c[3])
        : "r"(a[0]), "r"(a[1]), "r"(a[2]), "r"(a[3]), "r"(b[0]), "r"(b[1]));
}

// ======================= W transpose + bf16 hi/lo split =======================
__global__ void convw_kernel(const float* __restrict__ w) {
    int idx = blockIdx.x * blockDim.x + threadIdx.x;   // over 512*256
    if (idx >= IN_DIM * OUT_DIM) return;
    int k = idx / OUT_DIM, n = idx % OUT_DIM;
    float f = w[idx];
    __nv_bfloat16 hi = __float2bfloat16_rn(f);
    float lof = f - __bfloat162float(hi);
    __nv_bfloat16 lo = __float2bfloat16_rn(lof);
    g_whiT[(size_t)n * IN_DIM + k] = hi;
    g_wloT[(size_t)n * IN_DIM + k] = lo;
}

// ======================= split-bf16 HMMA GEMM + tanh -> fp16 =======================
// CTA tile 128(M) x 128(N), BK=32, 8 warps in 4x2 (warp tile 32x64).
// SMEM rows padded to 40 bf16 (80 B, 16B-aligned, conflict-free ldmatrix).
#define GBK 32
#define GSTRIDE 40

__global__ __launch_bounds__(256, 1)
void gemm_mma_kernel(const float* __restrict__ x, const int* __restrict__ act_ptr, int M)
{
    __shared__ __align__(16) __nv_bfloat16 sAhi[128 * GSTRIDE];
    __shared__ __align__(16) __nv_bfloat16 sAlo[128 * GSTRIDE];
    __shared__ __align__(16) __nv_bfloat16 sBhi[128 * GSTRIDE];
    __shared__ __align__(16) __nv_bfloat16 sBlo[128 * GSTRIDE];

    const int tid = threadIdx.x;
    const int lane = tid & 31, wid = tid >> 5;
    const int bm = blockIdx.x * 128;
    const int bn = blockIdx.y * 128;
    const int wm = (wid & 3) * 32;    // warp M offset within CTA tile
    const int wn = (wid >> 2) * 64;   // warp N offset

    const uint32_t sAhi_b = smem_u32(sAhi);
    const uint32_t sAlo_b = smem_u32(sAlo);
    const uint32_t sBhi_b = smem_u32(sBhi);
    const uint32_t sBlo_b = smem_u32(sBlo);

    float acc[2][8][4];
    #pragma unroll
    for (int i = 0; i < 2; i++)
        #pragma unroll
        for (int j = 0; j < 8; j++)
            #pragma unroll
            for (int q = 0; q < 4; q++) acc[i][j][q] = 0.f;

    // precomputed ldmatrix lane addresses (element offsets; *2 for bytes)
    const int a_row = (lane & 15), a_koff = (lane >> 4) * 8;
    const int b_row = (lane & 7) + ((lane >> 4) & 1) * 8, b_koff = ((lane >> 3) & 1) * 8;

    for (int chunk = 0; chunk < IN_DIM / GBK; chunk++) {
        const int kk = chunk * GBK;

        // ---- A tile: 128 rows x 32 fp32 -> bf16 hi/lo. 1024 float4, 4/thread ----
        #pragma unroll
        for (int it = 0; it < 4; it++) {
            int i = tid + it * 256;
            int row = i >> 3, f4 = i & 7;
            float4 v = make_float4(0.f, 0.f, 0.f, 0.f);
            int grow = bm + row;
            if (grow < M)
                v = *(const float4*)(x + (size_t)grow * IN_DIM + kk + f4 * 4);
            __nv_bfloat16 hx = __float2bfloat16_rn(v.x), hy = __float2bfloat16_rn(v.y);
            __nv_bfloat16 hz = __float2bfloat16_rn(v.z), hw = __float2bfloat16_rn(v.w);
            __nv_bfloat16 lx = __float2bfloat16_rn(v.x - __bfloat162float(hx));
            __nv_bfloat16 ly = __float2bfloat16_rn(v.y - __bfloat162float(hy));
            __nv_bfloat16 lz = __float2bfloat16_rn(v.z - __bfloat162float(hz));
            __nv_bfloat16 lw = __float2bfloat16_rn(v.w - __bfloat162float(hw));
            __nv_bfloat162 h01(hx, hy), h23(hz, hw), l01(lx, ly), l23(lz, lw);
            int off = row * GSTRIDE + f4 * 4;
            *(uint2*)&sAhi[off] = make_uint2(*(uint32_t*)&h01, *(uint32_t*)&h23);
            *(uint2*)&sAlo[off] = make_uint2(*(uint32_t*)&l01, *(uint32_t*)&l23);
        }
        // ---- B tiles: 128 n-rows x 32 k bf16 (hi & lo). 512 uint4 each, 2/thread ----
        #pragma unroll
        for (int it = 0; it < 2; it++) {
            int i = tid + it * 256;
            int row = i >> 2, seg = i & 3;
            size_t gsrc = (size_t)(bn + row) * IN_DIM + kk + seg * 8;
            int off = row * GSTRIDE + seg * 8;
            *(uint4*)&sBhi[off] = *(const uint4*)(g_whiT + gsrc);
            *(uint4*)&sBlo[off] = *(const uint4*)(g_wloT + gsrc);
        }
        __syncthreads();

        #pragma unroll
        for (int ks = 0; ks < 2; ks++) {
            const int k0 = ks * 16;
            uint32_t ah[2][4], al[2][4];
            #pragma unroll
            for (int mt = 0; mt < 2; mt++) {
                uint32_t eoff = (uint32_t)((wm + mt * 16 + a_row) * GSTRIDE + k0 + a_koff) * 2u;
                ldmx4(ah[mt][0], ah[mt][1], ah[mt][2], ah[mt][3], sAhi_b + eoff);
                ldmx4(al[mt][0], al[mt][1], al[mt][2], al[mt][3], sAlo_b + eoff);
            }
            #pragma unroll
            for (int nt2 = 0; nt2 < 4; nt2++) {
                uint32_t eoff = (uint32_t)((wn + nt2 * 16 + b_row) * GSTRIDE + k0 + b_koff) * 2u;
                uint32_t bh[4], bl[4];
                ldmx4(bh[0], bh[1], bh[2], bh[3], sBhi_b + eoff);
                ldmx4(bl[0], bl[1], bl[2], bl[3], sBlo_b + eoff);
                #pragma unroll
                for (int mt = 0; mt < 2; mt++) {
                    #pragma unroll
                    for (int j = 0; j < 2; j++) {
                        float* c = acc[mt][nt2 * 2 + j];
                        const uint32_t* bfh = &bh[j * 2];
                        const uint32_t* bfl = &bl[j * 2];
                        mma_bf16(c, ah[mt], bfh);   // hi*hi
                        mma_bf16(c, ah[mt], bfl);   // hi*lo
                        mma_bf16(c, al[mt], bfh);   // lo*hi
                    }
                }
            }
        }
        __syncthreads();
    }

    // ---- epilogue: tanh -> fp16 ----
    const int act = act_ptr ? act_ptr[0] : 1;
    #pragma unroll
    for (int mt = 0; mt < 2; mt++) {
        int r0 = bm + wm + mt * 16 + (lane >> 2);
        #pragma unroll
        for (int nt = 0; nt < 8; nt++) {
            int col = bn + wn + nt * 8 + (lane & 3) * 2;
            float c0 = acc[mt][nt][0], c1 = acc[mt][nt][1];
            float c2 = acc[mt][nt][2], c3 = acc[mt][nt][3];
            if (act) { c0 = tanhf(c0); c1 = tanhf(c1); c2 = tanhf(c2); c3 = tanhf(c3); }
            if (r0 < M)
                *(__half2*)(g_support_h + (size_t)r0 * OUT_DIM + col) = __floats2half2_rn(c0, c1);
            if (r0 + 8 < M)
                *(__half2*)(g_support_h + (size_t)(r0 + 8) * OUT_DIM + col) = __floats2half2_rn(c2, c3);
        }
    }
}

// ======================= CSR build =======================
__global__ void zero_counts(int N) {
    int i = blockIdx.x * blockDim.x + threadIdx.x;
    if (i < N) g_count[i] = 0;
}

__global__ void hist_kernel(const int* __restrict__ rows, int E) {
    int i = blockIdx.x * blockDim.x + threadIdx.x;
    int i4 = i * 4;
    if (i4 + 3 < E) {
        int4 r = *(const int4*)(rows + i4);
        atomicAdd(&g_count[r.x], 1);
        atomicAdd(&g_count[r.y], 1);
        atomicAdd(&g_count[r.z], 1);
        atomicAdd(&g_count[r.w], 1);
    } else {
        for (int j = i4; j < E; j++) atomicAdd(&g_count[rows[j]], 1);
    }
}

// -- parallel scan, 3 phases, 1024 counts per block --
__global__ __launch_bounds__(1024) void scan_phase1(int N) {
    __shared__ int ws[32];
    int b = blockIdx.x, tid = threadIdx.x, lane = tid & 31, wid = tid >> 5;
    int i = b * 1024 + tid;
    int v = (i < N) ? g_count[i] : 0;
    #pragma unroll
    for (int o = 16; o > 0; o >>= 1) v += __shfl_down_sync(0xFFFFFFFFu, v, o);
    if (lane == 0) ws[wid] = v;
    __syncthreads();
    if (wid == 0) {
        int s = ws[lane];
        #pragma unroll
        for (int o = 16; o > 0; o >>= 1) s += __shfl_down_sync(0xFFFFFFFFu, s, o);
        if (lane == 0) g_blocksum[b] = s;
    }
}

__global__ __launch_bounds__(128) void scan_phase2(int NB) {
    __shared__ int ws[4];
    int tid = threadIdx.x, lane = tid & 31, wid = tid >> 5;
    int v = (tid < NB) ? g_blocksum[tid] : 0;
    int xv = v;
    #pragma unroll
    for (int o = 1; o < 32; o <<= 1) {
        int t = __shfl_up_sync(0xFFFFFFFFu, xv, o);
        if (lane >= o) xv += t;
    }
    if (lane == 31) ws[wid] = xv;
    __syncthreads();
    int carry = 0;
    #pragma unroll
    for (int w = 0; w < 4; w++) { if (w < wid) carry += ws[w]; }
    if (tid < NB) g_blockoff[tid] = carry + xv - v;   // exclusive
}

__global__ __launch_bounds__(1024) void scan_phase3(int N, int E) {
    __shared__ int ws[32];
    int b = blockIdx.x, tid = threadIdx.x, lane = tid & 31, wid = tid >> 5;
    int i = b * 1024 + tid;
    int v = (i < N) ? g_count[i] : 0;
    int xv = v;
    #pragma unroll
    for (int o = 1; o < 32; o <<= 1) {
        int t = __shfl_up_sync(0xFFFFFFFFu, xv, o);
        if (lane >= o) xv += t;
    }
    if (lane == 31) ws[wid] = xv;
    __syncthreads();
    if (wid == 0) {
        int wv = ws[lane];
        int y = wv;
        #pragma unroll
        for (int o = 1; o < 32; o <<= 1) {
            int t = __shfl_up_sync(0xFFFFFFFFu, y, o);
            if (lane >= o) y += t;
        }
        ws[lane] = y - wv;   // exclusive warp offsets
    }
    __syncthreads();
    int off = g_blockoff[b] + ws[wid] + xv - v;   // global exclusive prefix
    if (i < N) { g_rowstart[i] = off; g_cursor[i] = off; }
    if (i == N - 1) g_rowstart[N] = off + v;      // == E
}

__global__ void scatter_kernel(const int* __restrict__ rows,
                               const int* __restrict__ cols,
                               const float* __restrict__ vals, int E) {
    int i = blockIdx.x * blockDim.x + threadIdx.x;
    if (i < E) {
        int r = rows[i];
        int p = atomicAdd(&g_cursor[r], 1);
        g_edge[p] = make_int2(cols[i], __float_as_int(vals[i]));
    }
}

// ======================= SpMM (fp16 gather, warp per row, MLP=4) =======================
__global__ __launch_bounds__(256) void spmm_kernel(float* __restrict__ out, int N) {
    int wrow = (blockIdx.x * blockDim.x + threadIdx.x) >> 5;
    int lane = threadIdx.x & 31;
    if (wrow >= N) return;
    int s = g_rowstart[wrow];
    int e = g_rowstart[wrow + 1];
    float a0 = 0.f, a1 = 0.f, a2 = 0.f, a3 = 0.f;
    float a4 = 0.f, a5 = 0.f, a6 = 0.f, a7 = 0.f;
    const size_t loff = (size_t)lane * 8;
    int i = s;
    for (; i + 4 <= e; i += 4) {
        int2 e0 = g_edge[i],     e1 = g_edge[i + 1];
        int2 e2 = g_edge[i + 2], e3 = g_edge[i + 3];
        uint4 q0 = *(const uint4*)(g_support_h + (size_t)e0.x * OUT_DIM + loff);
        uint4 q1 = *(const uint4*)(g_support_h + (size_t)e1.x * OUT_DIM + loff);
        uint4 q2 = *(const uint4*)(g_support_h + (size_t)e2.x * OUT_DIM + loff);
        uint4 q3 = *(const uint4*)(g_support_h + (size_t)e3.x * OUT_DIM + loff);
        float v0 = __int_as_float(e0.y), v1 = __int_as_float(e1.y);
        float v2 = __int_as_float(e2.y), v3 = __int_as_float(e3.y);
        {
            float2 f0 = __half22float2(*(const __half2*)&q0.x);
            float2 f1 = __half22float2(*(const __half2*)&q0.y);
            float2 f2 = __half22float2(*(const __half2*)&q0.z);
            float2 f3 = __half22float2(*(const __half2*)&q0.w);
            a0 += v0 * f0.x; a1 += v0 * f0.y; a2 += v0 * f1.x; a3 += v0 * f1.y;
            a4 += v0 * f2.x; a5 += v0 * f2.y; a6 += v0 * f3.x; a7 += v0 * f3.y;
        }
        {
            float2 f0 = __half22float2(*(const __half2*)&q1.x);
            float2 f1 = __half22float2(*(const __half2*)&q1.y);
            float2 f2 = __half22float2(*(const __half2*)&q1.z);
            float2 f3 = __half22float2(*(const __half2*)&q1.w);
            a0 += v1 * f0.x; a1 += v1 * f0.y; a2 += v1 * f1.x; a3 += v1 * f1.y;
            a4 += v1 * f2.x; a5 += v1 * f2.y; a6 += v1 * f3.x; a7 += v1 * f3.y;
        }
        {
            float2 f0 = __half22float2(*(const __half2*)&q2.x);
            float2 f1 = __half22float2(*(const __half2*)&q2.y);
            float2 f2 = __half22float2(*(const __half2*)&q2.z);
            float2 f3 = __half22float2(*(const __half2*)&q2.w);
            a0 += v2 * f0.x; a1 += v2 * f0.y; a2 += v2 * f1.x; a3 += v2 * f1.y;
            a4 += v2 * f2.x; a5 += v2 * f2.y; a6 += v2 * f3.x; a7 += v2 * f3.y;
        }
        {
            float2 f0 = __half22float2(*(const __half2*)&q3.x);
            float2 f1 = __half22float2(*(const __half2*)&q3.y);
            float2 f2 = __half22float2(*(const __half2*)&q3.z);
            float2 f3 = __half22float2(*(const __half2*)&q3.w);
            a0 += v3 * f0.x; a1 += v3 * f0.y; a2 += v3 * f1.x; a3 += v3 * f1.y;
            a4 += v3 * f2.x; a5 += v3 * f2.y; a6 += v3 * f3.x; a7 += v3 * f3.y;
        }
    }
    for (; i < e; i++) {
        int2 ed = g_edge[i];
        float v = __int_as_float(ed.y);
        uint4 q = *(const uint4*)(g_support_h + (size_t)ed.x * OUT_DIM + loff);
        float2 f0 = __half22float2(*(const __half2*)&q.x);
        float2 f1 = __half22float2(*(const __half2*)&q.y);
        float2 f2 = __half22float2(*(const __half2*)&q.z);
        float2 f3 = __half22float2(*(const __half2*)&q.w);
        a0 += v * f0.x; a1 += v * f0.y; a2 += v * f1.x; a3 += v * f1.y;
        a4 += v * f2.x; a5 += v * f2.y; a6 += v * f3.x; a7 += v * f3.y;
    }
    float* op = out + (size_t)wrow * OUT_DIM + lane * 8;
    *(float4*)(op)     = make_float4(a0, a1, a2, a3);
    *(float4*)(op + 4) = make_float4(a4, a5, a6, a7);
}

// ======================= launch =======================
extern "C" void kernel_launch(void* const* d_in, const int* in_sizes, int n_in,
                              void* d_out, int out_size) {
    const float* x    = (const float*)d_in[0];
    const float* w    = (const float*)d_in[1];
    const int*   erow = (const int*)d_in[2];
    const int*   ecol = (const int*)d_in[3];
    const float* eval = (const float*)d_in[4];
    const int*   act  = (n_in > 5) ? (const int*)d_in[5] : nullptr;

    int M = in_sizes[0] / IN_DIM;   // 100000
    int E = in_sizes[2];            // 3200000
    float* out = (float*)d_out;

    // ---- fork: CSR build on g_sB, GEMM chain on stream 0 ----
    cudaEventRecord(g_evFork, 0);
    cudaStreamWaitEvent(g_sB, g_evFork, 0);

    // stream 0: convw -> gemm
    convw_kernel<<<(IN_DIM * OUT_DIM + 255) / 256, 256>>>(w);
    dim3 ggrid((M + 127) / 128, OUT_DIM / 128);
    gemm_mma_kernel<<<ggrid, 256>>>(x, act, M);

    // stream B: zero -> hist -> scan -> scatter
    zero_counts<<<(M + 255) / 256, 256, 0, g_sB>>>(M);
    hist_kernel<<<(E / 4 + 255) / 256, 256, 0, g_sB>>>(erow, E);
    int NB = (M + 1023) / 1024;     // 98
    scan_phase1<<<NB, 1024, 0, g_sB>>>(M);
    scan_phase2<<<1, 128, 0, g_sB>>>(NB);
    scan_phase3<<<NB, 1024, 0, g_sB>>>(M, E);
    scatter_kernel<<<(E + 255) / 256, 256, 0, g_sB>>>(erow, ecol, eval, E);

    // ---- join, then SpMM on stream 0 ----
    cudaEventRecord(g_evJoin, g_sB);
    cudaStreamWaitEvent(0, g_evJoin, 0);

    long long spmm_threads = (long long)M * 32;
    spmm_kernel<<<(unsigned)((spmm_threads + 255) / 256), 256>>>(out, M);
}

// round 10
// speedup vs baseline: 2.4676x; 1.1401x over previous
#include <cuda_runtime.h>
#include <cuda_fp16.h>
#include <cuda_bf16.h>
#include <cstdint>

#define MAXN 100000
#define MAXE 3200000
#define IN_DIM 512
#define OUT_DIM 256

// ---------------- scratch (static __device__, no runtime allocation) ----------------
__device__ __half          g_support_h[(size_t)MAXN * OUT_DIM];   // tanh(x@W) in fp16, 51.2 MB
__device__ __nv_bfloat16   g_whiT[(size_t)OUT_DIM * IN_DIM];      // W^T hi  [256][512]
__device__ __nv_bfloat16   g_wloT[(size_t)OUT_DIM * IN_DIM];      // W^T lo
__device__ int   g_count[MAXN];
__device__ int   g_rowstart[MAXN + 1];
__device__ int   g_cursor[MAXN];
__device__ int2  g_edge[MAXE];          // packed (col, val-bits)
__device__ int   g_blocksum[128];
__device__ int   g_blockoff[128];

// ---------------- host-side stream/event objects (created at load, before capture) ----------------
static cudaStream_t g_sB;
static cudaEvent_t  g_evFork, g_evG0, g_evScat, g_evS0;
struct _InitStreams {
    _InitStreams() {
        cudaStreamCreate(&g_sB);
        cudaEventCreateWithFlags(&g_evFork, cudaEventDisableTiming);
        cudaEventCreateWithFlags(&g_evG0,   cudaEventDisableTiming);
        cudaEventCreateWithFlags(&g_evScat, cudaEventDisableTiming);
        cudaEventCreateWithFlags(&g_evS0,   cudaEventDisableTiming);
    }
};
static _InitStreams g_init_streams;

// ======================= helpers =======================
__device__ __forceinline__ uint32_t smem_u32(const void* p) {
    uint32_t a;
    asm("{ .reg .u64 t; cvta.to.shared.u64 t, %1; cvt.u32.u64 %0, t; }" : "=r"(a) : "l"(p));
    return a;
}

__device__ __forceinline__ void ldmx4(uint32_t& r0, uint32_t& r1, uint32_t& r2, uint32_t& r3,
                                      uint32_t addr) {
    asm volatile("ldmatrix.sync.aligned.m8n8.x4.shared.b16 {%0,%1,%2,%3}, [%4];"
                 : "=r"(r0), "=r"(r1), "=r"(r2), "=r"(r3) : "r"(addr));
}

__device__ __forceinline__ void mma_bf16(float* c, const uint32_t* a, const uint32_t* b) {
    asm volatile(
        "mma.sync.aligned.m16n8k16.row.col.f32.bf16.bf16.f32 "
        "{%0,%1,%2,%3}, {%4,%5,%6,%7}, {%8,%9}, {%0,%1,%2,%3};"
        : "+f"(c[0]), "+f"(c[1]), "+f"(c[2]), "+f"(c[3])
        : "r"(a[0]), "r"(a[1]), "r"(a[2]), "r"(a[3]), "r"(b[0]), "r"(b[1]));
}

// ======================= W transpose + bf16 hi/lo split =======================
__global__ void convw_kernel(const float* __restrict__ w) {
    int idx = blockIdx.x * blockDim.x + threadIdx.x;   // over 512*256
    if (idx >= IN_DIM * OUT_DIM) return;
    int k = idx / OUT_DIM, n = idx % OUT_DIM;
    float f = w[idx];
    __nv_bfloat16 hi = __float2bfloat16_rn(f);
    float lof = f - __bfloat162float(hi);
    __nv_bfloat16 lo = __float2bfloat16_rn(lof);
    g_whiT[(size_t)n * IN_DIM + k] = hi;
    g_wloT[(size_t)n * IN_DIM + k] = lo;
}

// ======================= split-bf16 HMMA GEMM + tanh -> fp16 =======================
// CTA tile 128(M) x 128(N), BK=32, 8 warps in 4x2 (warp tile 32x64).
// N half selected via n_base (two launches). A tile register-prefetched.
#define GBK 32
#define GSTRIDE 40
#define NCHUNK (IN_DIM / GBK)

__global__ __launch_bounds__(256)
void gemm_mma_kernel(const float* __restrict__ x, const int* __restrict__ act_ptr,
                     int M, int n_base)
{
    __shared__ __align__(16) __nv_bfloat16 sAhi[128 * GSTRIDE];
    __shared__ __align__(16) __nv_bfloat16 sAlo[128 * GSTRIDE];
    __shared__ __align__(16) __nv_bfloat16 sBhi[128 * GSTRIDE];
    __shared__ __align__(16) __nv_bfloat16 sBlo[128 * GSTRIDE];

    const int tid = threadIdx.x;
    const int lane = tid & 31, wid = tid >> 5;
    const int bm = blockIdx.x * 128;
    const int bn = n_base;
    const int wm = (wid & 3) * 32;    // warp M offset within CTA tile
    const int wn = (wid >> 2) * 64;   // warp N offset

    const uint32_t sAhi_b = smem_u32(sAhi);
    const uint32_t sAlo_b = smem_u32(sAlo);
    const uint32_t sBhi_b = smem_u32(sBhi);
    const uint32_t sBlo_b = smem_u32(sBlo);

    float acc[2][8][4];
    #pragma unroll
    for (int i = 0; i < 2; i++)
        #pragma unroll
        for (int j = 0; j < 8; j++)
            #pragma unroll
            for (int q = 0; q < 4; q++) acc[i][j][q] = 0.f;

    // A-tile load geometry: 1024 float4, 4 per thread
    const int a_ld_row = tid >> 3, a_ld_f4 = tid & 7;   // rows step by 32 per it
    // ldmatrix lane addressing
    const int a_row = (lane & 15), a_koff = (lane >> 4) * 8;
    const int b_row = (lane & 7) + ((lane >> 4) & 1) * 8, b_koff = ((lane >> 3) & 1) * 8;

    // ---- prefetch chunk 0 A into registers ----
    float4 pref[4];
    #pragma unroll
    for (int it = 0; it < 4; it++) {
        int grow = bm + a_ld_row + it * 32;
        pref[it] = make_float4(0.f, 0.f, 0.f, 0.f);
        if (grow < M)
            pref[it] = *(const float4*)(x + (size_t)grow * IN_DIM + a_ld_f4 * 4);
    }

    for (int chunk = 0; chunk < NCHUNK; chunk++) {
        // ---- convert & store prefetched A ----
        #pragma unroll
        for (int it = 0; it < 4; it++) {
            float4 v = pref[it];
            __nv_bfloat16 hx = __float2bfloat16_rn(v.x), hy = __float2bfloat16_rn(v.y);
            __nv_bfloat16 hz = __float2bfloat16_rn(v.z), hw = __float2bfloat16_rn(v.w);
            __nv_bfloat16 lx = __float2bfloat16_rn(v.x - __bfloat162float(hx));
            __nv_bfloat16 ly = __float2bfloat16_rn(v.y - __bfloat162float(hy));
            __nv_bfloat16 lz = __float2bfloat16_rn(v.z - __bfloat162float(hz));
            __nv_bfloat16 lw = __float2bfloat16_rn(v.w - __bfloat162float(hw));
            __nv_bfloat162 h01(hx, hy), h23(hz, hw), l01(lx, ly), l23(lz, lw);
            int off = (a_ld_row + it * 32) * GSTRIDE + a_ld_f4 * 4;
            *(uint2*)&sAhi[off] = make_uint2(*(uint32_t*)&h01, *(uint32_t*)&h23);
            *(uint2*)&sAlo[off] = make_uint2(*(uint32_t*)&l01, *(uint32_t*)&l23);
        }
        // ---- B tiles (L2-resident W): 2 uint4 per thread each buffer ----
        {
            const int kk = chunk * GBK;
            #pragma unroll
            for (int it = 0; it < 2; it++) {
                int i = tid + it * 256;
                int row = i >> 2, seg = i & 3;
                size_t gsrc = (size_t)(bn + row) * IN_DIM + kk + seg * 8;
                int off = row * GSTRIDE + seg * 8;
                *(uint4*)&sBhi[off] = *(const uint4*)(g_whiT + gsrc);
                *(uint4*)&sBlo[off] = *(const uint4*)(g_wloT + gsrc);
            }
        }
        __syncthreads();

        // ---- issue next chunk's A loads (overlap with MMA below) ----
        if (chunk + 1 < NCHUNK) {
            const int kk = (chunk + 1) * GBK;
            #pragma unroll
            for (int it = 0; it < 4; it++) {
                int grow = bm + a_ld_row + it * 32;
                pref[it] = make_float4(0.f, 0.f, 0.f, 0.f);
                if (grow < M)
                    pref[it] = *(const float4*)(x + (size_t)grow * IN_DIM + kk + a_ld_f4 * 4);
            }
        }

        #pragma unroll
        for (int ks = 0; ks < 2; ks++) {
            const int k0 = ks * 16;
            uint32_t ah[2][4], al[2][4];
            #pragma unroll
            for (int mt = 0; mt < 2; mt++) {
                uint32_t eoff = (uint32_t)((wm + mt * 16 + a_row) * GSTRIDE + k0 + a_koff) * 2u;
                ldmx4(ah[mt][0], ah[mt][1], ah[mt][2], ah[mt][3], sAhi_b + eoff);
                ldmx4(al[mt][0], al[mt][1], al[mt][2], al[mt][3], sAlo_b + eoff);
            }
            #pragma unroll
            for (int nt2 = 0; nt2 < 4; nt2++) {
                uint32_t eoff = (uint32_t)((wn + nt2 * 16 + b_row) * GSTRIDE + k0 + b_koff) * 2u;
                uint32_t bh[4], bl[4];
                ldmx4(bh[0], bh[1], bh[2], bh[3], sBhi_b + eoff);
                ldmx4(bl[0], bl[1], bl[2], bl[3], sBlo_b + eoff);
                #pragma unroll
                for (int mt = 0; mt < 2; mt++) {
                    #pragma unroll
                    for (int j = 0; j < 2; j++) {
                        float* c = acc[mt][nt2 * 2 + j];
                        const uint32_t* bfh = &bh[j * 2];
                        const uint32_t* bfl = &bl[j * 2];
                        mma_bf16(c, ah[mt], bfh);   // hi*hi
                        mma_bf16(c, ah[mt], bfl);   // hi*lo
                        mma_bf16(c, al[mt], bfh);   // lo*hi
                    }
                }
            }
        }
        __syncthreads();
    }

    // ---- epilogue: tanh -> fp16 ----
    const int act = act_ptr ? act_ptr[0] : 1;
    #pragma unroll
    for (int mt = 0; mt < 2; mt++) {
        int r0 = bm + wm + mt * 16 + (lane >> 2);
        #pragma unroll
        for (int nt = 0; nt < 8; nt++) {
            int col = bn + wn + nt * 8 + (lane & 3) * 2;
            float c0 = acc[mt][nt][0], c1 = acc[mt][nt][1];
            float c2 = acc[mt][nt][2], c3 = acc[mt][nt][3];
            if (act) { c0 = tanhf(c0); c1 = tanhf(c1); c2 = tanhf(c2); c3 = tanhf(c3); }
            if (r0 < M)
                *(__half2*)(g_support_h + (size_t)r0 * OUT_DIM + col) = __floats2half2_rn(c0, c1);
            if (r0 + 8 < M)
                *(__half2*)(g_support_h + (size_t)(r0 + 8) * OUT_DIM + col) = __floats2half2_rn(c2, c3);
        }
    }
}

// ======================= CSR build =======================
__global__ void zero_counts(int N) {
    int i = blockIdx.x * blockDim.x + threadIdx.x;
    if (i < N) g_count[i] = 0;
}

__global__ void hist_kernel(const int* __restrict__ rows, int E) {
    int i = blockIdx.x * blockDim.x + threadIdx.x;
    int i4 = i * 4;
    if (i4 + 3 < E) {
        int4 r = *(const int4*)(rows + i4);
        atomicAdd(&g_count[r.x], 1);
        atomicAdd(&g_count[r.y], 1);
        atomicAdd(&g_count[r.z], 1);
        atomicAdd(&g_count[r.w], 1);
    } else {
        for (int j = i4; j < E; j++) atomicAdd(&g_count[rows[j]], 1);
    }
}

// -- parallel scan, 3 phases, 1024 counts per block --
__global__ __launch_bounds__(1024) void scan_phase1(int N) {
    __shared__ int ws[32];
    int b = blockIdx.x, tid = threadIdx.x, lane = tid & 31, wid = tid >> 5;
    int i = b * 1024 + tid;
    int v = (i < N) ? g_count[i] : 0;
    #pragma unroll
    for (int o = 16; o > 0; o >>= 1) v += __shfl_down_sync(0xFFFFFFFFu, v, o);
    if (lane == 0) ws[wid] = v;
    __syncthreads();
    if (wid == 0) {
        int s = ws[lane];
        #pragma unroll
        for (int o = 16; o > 0; o >>= 1) s += __shfl_down_sync(0xFFFFFFFFu, s, o);
        if (lane == 0) g_blocksum[b] = s;
    }
}

__global__ __launch_bounds__(128) void scan_phase2(int NB) {
    __shared__ int ws[4];
    int tid = threadIdx.x, lane = tid & 31, wid = tid >> 5;
    int v = (tid < NB) ? g_blocksum[tid] : 0;
    int xv = v;
    #pragma unroll
    for (int o = 1; o < 32; o <<= 1) {
        int t = __shfl_up_sync(0xFFFFFFFFu, xv, o);
        if (lane >= o) xv += t;
    }
    if (lane == 31) ws[wid] = xv;
    __syncthreads();
    int carry = 0;
    #pragma unroll
    for (int w = 0; w < 4; w++) { if (w < wid) carry += ws[w]; }
    if (tid < NB) g_blockoff[tid] = carry + xv - v;   // exclusive
}

__global__ __launch_bounds__(1024) void scan_phase3(int N, int E) {
    __shared__ int ws[32];
    int b = blockIdx.x, tid = threadIdx.x, lane = tid & 31, wid = tid >> 5;
    int i = b * 1024 + tid;
    int v = (i < N) ? g_count[i] : 0;
    int xv = v;
    #pragma unroll
    for (int o = 1; o < 32; o <<= 1) {
        int t = __shfl_up_sync(0xFFFFFFFFu, xv, o);
        if (lane >= o) xv += t;
    }
    if (lane == 31) ws[wid] = xv;
    __syncthreads();
    if (wid == 0) {
        int wv = ws[lane];
        int y = wv;
        #pragma unroll
        for (int o = 1; o < 32; o <<= 1) {
            int t = __shfl_up_sync(0xFFFFFFFFu, y, o);
            if (lane >= o) y += t;
        }
        ws[lane] = y - wv;   // exclusive warp offsets
    }
    __syncthreads();
    int off = g_blockoff[b] + ws[wid] + xv - v;   // global exclusive prefix
    if (i < N) { g_rowstart[i] = off; g_cursor[i] = off; }
    if (i == N - 1) g_rowstart[N] = off + v;      // == E
}

__global__ void scatter_kernel(const int* __restrict__ rows,
                               const int* __restrict__ cols,
                               const float* __restrict__ vals, int E) {
    int i = blockIdx.x * blockDim.x + threadIdx.x;
    if (i < E) {
        int r = rows[i];
        int p = atomicAdd(&g_cursor[r], 1);
        g_edge[p] = make_int2(cols[i], __float_as_int(vals[i]));
    }
}

// ======================= SpMM half (128 output cols), warp per row, MLP=4 =======================
__global__ __launch_bounds__(256)
void spmm_half_kernel(float* __restrict__ out, int N, int colbase) {
    int wrow = (blockIdx.x * blockDim.x + threadIdx.x) >> 5;
    int lane = threadIdx.x & 31;
    if (wrow >= N) return;
    int s = g_rowstart[wrow];
    int e = g_rowstart[wrow + 1];
    float a0 = 0.f, a1 = 0.f, a2 = 0.f, a3 = 0.f;
    const size_t loff = (size_t)colbase + lane * 4;
    int i = s;
    for (; i + 4 <= e; i += 4) {
        int2 e0 = g_edge[i],     e1 = g_edge[i + 1];
        int2 e2 = g_edge[i + 2], e3 = g_edge[i + 3];
        uint2 q0 = *(const uint2*)(g_support_h + (size_t)e0.x * OUT_DIM + loff);
        uint2 q1 = *(const uint2*)(g_support_h + (size_t)e1.x * OUT_DIM + loff);
        uint2 q2 = *(const uint2*)(g_support_h + (size_t)e2.x * OUT_DIM + loff);
        uint2 q3 = *(const uint2*)(g_support_h + (size_t)e3.x * OUT_DIM + loff);
        float v0 = __int_as_float(e0.y), v1 = __int_as_float(e1.y);
        float v2 = __int_as_float(e2.y), v3 = __int_as_float(e3.y);
        {
            float2 f0 = __half22float2(*(const __half2*)&q0.x);
            float2 f1 = __half22float2(*(const __half2*)&q0.y);
            a0 += v0 * f0.x; a1 += v0 * f0.y; a2 += v0 * f1.x; a3 += v0 * f1.y;
        }
        {
            float2 f0 = __half22float2(*(const __half2*)&q1.x);
            float2 f1 = __half22float2(*(const __half2*)&q1.y);
            a0 += v1 * f0.x; a1 += v1 * f0.y; a2 += v1 * f1.x; a3 += v1 * f1.y;
        }
        {
            float2 f0 = __half22float2(*(const __half2*)&q2.x);
            float2 f1 = __half22float2(*(const __half2*)&q2.y);
            a0 += v2 * f0.x; a1 += v2 * f0.y; a2 += v2 * f1.x; a3 += v2 * f1.y;
        }
        {
            float2 f0 = __half22float2(*(const __half2*)&q3.x);
            float2 f1 = __half22float2(*(const __half2*)&q3.y);
            a0 += v3 * f0.x; a1 += v3 * f0.y; a2 += v3 * f1.x; a3 += v3 * f1.y;
        }
    }
    for (; i < e; i++) {
        int2 ed = g_edge[i];
        float v = __int_as_float(ed.y);
        uint2 q = *(const uint2*)(g_support_h + (size_t)ed.x * OUT_DIM + loff);
        float2 f0 = __half22float2(*(const __half2*)&q.x);
        float2 f1 = __half22float2(*(const __half2*)&q.y);
        a0 += v * f0.x; a1 += v * f0.y; a2 += v * f1.x; a3 += v * f1.y;
    }
    *(float4*)(out + (size_t)wrow * OUT_DIM + loff) = make_float4(a0, a1, a2, a3);
}

// ======================= launch =======================
extern "C" void kernel_launch(void* const* d_in, const int* in_sizes, int n_in,
                              void* d_out, int out_size) {
    const float* x    = (const float*)d_in[0];
    const float* w    = (const float*)d_in[1];
    const int*   erow = (const int*)d_in[2];
    const int*   ecol = (const int*)d_in[3];
    const float* eval = (const float*)d_in[4];
    const int*   act  = (n_in > 5) ? (const int*)d_in[5] : nullptr;

    int M = in_sizes[0] / IN_DIM;   // 100000
    int E = in_sizes[2];            // 3200000
    float* out = (float*)d_out;

    // ---- fork ----
    cudaEventRecord(g_evFork, 0);
    cudaStreamWaitEvent(g_sB, g_evFork, 0);

    // stream 0: convw -> gemm half 0 -> gemm half 1
    convw_kernel<<<(IN_DIM * OUT_DIM + 255) / 256, 256>>>(w);
    int gtiles = (M + 127) / 128;
    gemm_mma_kernel<<<gtiles, 256>>>(x, act, M, 0);
    cudaEventRecord(g_evG0, 0);
    gemm_mma_kernel<<<gtiles, 256>>>(x, act, M, 128);

    // stream B: CSR chain
    zero_counts<<<(M + 255) / 256, 256, 0, g_sB>>>(M);
    hist_kernel<<<(E / 4 + 255) / 256, 256, 0, g_sB>>>(erow, E);
    int NB = (M + 1023) / 1024;     // 98
    scan_phase1<<<NB, 1024, 0, g_sB>>>(M);
    scan_phase2<<<1, 128, 0, g_sB>>>(NB);
    scan_phase3<<<NB, 1024, 0, g_sB>>>(M, E);
    scatter_kernel<<<(E + 255) / 256, 256, 0, g_sB>>>(erow, ecol, eval, E);
    cudaEventRecord(g_evScat, g_sB);

    // stream B: spmm half 0 (needs gemm0 + scatter) — overlaps gemm half 1
    cudaStreamWaitEvent(g_sB, g_evG0, 0);
    long long spmm_threads = (long long)M * 32;
    unsigned spmm_blocks = (unsigned)((spmm_threads + 255) / 256);
    spmm_half_kernel<<<spmm_blocks, 256, 0, g_sB>>>(out, M, 0);
    cudaEventRecord(g_evS0, g_sB);

    // stream 0: spmm half 1 (needs gemm1 + scatter), then join
    cudaStreamWaitEvent(0, g_evScat, 0);
    spmm_half_kernel<<<spmm_blocks, 256>>>(out, M, 128);
    cudaStreamWaitEvent(0, g_evS0, 0);
}

// round 11
// speedup vs baseline: 2.4814x; 1.0056x over previous
#include <cuda_runtime.h>
#include <cuda_fp16.h>
#include <cuda_bf16.h>
#include <cstdint>

#define MAXN 100000
#define MAXE 3200000
#define IN_DIM 512
#define OUT_DIM 256

// ---------------- scratch (static __device__, no runtime allocation) ----------------
__device__ __half g_support_h[(size_t)MAXN * OUT_DIM];   // tanh(x@W) in fp16, 51.2 MB
__device__ __half g_wT[(size_t)OUT_DIM * IN_DIM];        // W^T fp16 [256][512]
__device__ int   g_count[MAXN];
__device__ int   g_rowstart[MAXN + 1];
__device__ int   g_cursor[MAXN];
__device__ int2  g_edge[MAXE];          // packed (col, val-bits)
__device__ int   g_blocksum[128];
__device__ int   g_blockoff[128];

// ---------------- host-side stream/event objects (created at load, before capture) ----------------
static cudaStream_t g_sB;
static cudaEvent_t  g_evFork, g_evG0, g_evScat, g_evS0;
struct _InitStreams {
    _InitStreams() {
        cudaStreamCreate(&g_sB);
        cudaEventCreateWithFlags(&g_evFork, cudaEventDisableTiming);
        cudaEventCreateWithFlags(&g_evG0,   cudaEventDisableTiming);
        cudaEventCreateWithFlags(&g_evScat, cudaEventDisableTiming);
        cudaEventCreateWithFlags(&g_evS0,   cudaEventDisableTiming);
    }
};
static _InitStreams g_init_streams;

// ======================= helpers =======================
__device__ __forceinline__ uint32_t smem_u32(const void* p) {
    uint32_t a;
    asm("{ .reg .u64 t; cvta.to.shared.u64 t, %1; cvt.u32.u64 %0, t; }" : "=r"(a) : "l"(p));
    return a;
}

__device__ __forceinline__ void ldmx4(uint32_t& r0, uint32_t& r1, uint32_t& r2, uint32_t& r3,
                                      uint32_t addr) {
    asm volatile("ldmatrix.sync.aligned.m8n8.x4.shared.b16 {%0,%1,%2,%3}, [%4];"
                 : "=r"(r0), "=r"(r1), "=r"(r2), "=r"(r3) : "r"(addr));
}

__device__ __forceinline__ void mma_f16(float* c, const uint32_t* a, const uint32_t* b) {
    asm volatile(
        "mma.sync.aligned.m16n8k16.row.col.f32.f16.f16.f32 "
        "{%0,%1,%2,%3}, {%4,%5,%6,%7}, {%8,%9}, {%0,%1,%2,%3};"
        : "+f"(c[0]), "+f"(c[1]), "+f"(c[2]), "+f"(c[3])
        : "r"(a[0]), "r"(a[1]), "r"(a[2]), "r"(a[3]), "r"(b[0]), "r"(b[1]));
}

// ======================= W transpose -> fp16 =======================
__global__ void convw_kernel(const float* __restrict__ w) {
    int idx = blockIdx.x * blockDim.x + threadIdx.x;   // over 512*256
    if (idx >= IN_DIM * OUT_DIM) return;
    int k = idx / OUT_DIM, n = idx % OUT_DIM;
    g_wT[(size_t)n * IN_DIM + k] = __float2half_rn(w[idx]);
}

// ======================= single-pass fp16 HMMA GEMM + tanh -> fp16 =======================
// CTA tile 128(M) x 128(N), BK=64, 8 warps in 4x2 (warp tile 32x64).
// SMEM rows padded to 72 halfs (144 B) -> conflict-free ldmatrix.
// N half selected via n_base (two launches). A tile register-prefetched.
#define GBK 64
#define GSTRIDE 72
#define NCHUNK (IN_DIM / GBK)   // 8

__global__ __launch_bounds__(256)
void gemm_mma_kernel(const float* __restrict__ x, const int* __restrict__ act_ptr,
                     int M, int n_base)
{
    __shared__ __align__(16) __half sA[128 * GSTRIDE];   // 18 KB
    __shared__ __align__(16) __half sB[128 * GSTRIDE];   // 18 KB

    const int tid = threadIdx.x;
    const int lane = tid & 31, wid = tid >> 5;
    const int bm = blockIdx.x * 128;
    const int bn = n_base;
    const int wm = (wid & 3) * 32;    // warp M offset
    const int wn = (wid >> 2) * 64;   // warp N offset

    const uint32_t sA_b = smem_u32(sA);
    const uint32_t sB_b = smem_u32(sB);

    float acc[2][8][4];
    #pragma unroll
    for (int i = 0; i < 2; i++)
        #pragma unroll
        for (int j = 0; j < 8; j++)
            #pragma unroll
            for (int q = 0; q < 4; q++) acc[i][j][q] = 0.f;

    // A tile load geometry: 128 rows x 16 float4 = 2048 float4, 8 per thread
    const int a_ld_row = tid >> 4;    // 0..15, rows step by 16 per it
    const int a_ld_f4  = tid & 15;    // 0..15
    // ldmatrix lane addressing
    const int a_row = (lane & 15), a_koff = (lane >> 4) * 8;
    const int b_row = (lane & 7) + ((lane >> 4) & 1) * 8, b_koff = ((lane >> 3) & 1) * 8;

    // ---- prefetch chunk 0 A ----
    float4 pref[8];
    #pragma unroll
    for (int it = 0; it < 8; it++) {
        int grow = bm + a_ld_row + it * 16;
        pref[it] = make_float4(0.f, 0.f, 0.f, 0.f);
        if (grow < M)
            pref[it] = *(const float4*)(x + (size_t)grow * IN_DIM + a_ld_f4 * 4);
    }

    for (int chunk = 0; chunk < NCHUNK; chunk++) {
        // ---- convert & store prefetched A (fp32 -> fp16) ----
        #pragma unroll
        for (int it = 0; it < 8; it++) {
            float4 v = pref[it];
            __half2 h01 = __floats2half2_rn(v.x, v.y);
            __half2 h23 = __floats2half2_rn(v.z, v.w);
            int off = (a_ld_row + it * 16) * GSTRIDE + a_ld_f4 * 4;
            *(uint2*)&sA[off] = make_uint2(*(uint32_t*)&h01, *(uint32_t*)&h23);
        }
        // ---- B tile (L2-resident W^T fp16): 128 rows x 64 halfs = 1024 uint4, 4/thread ----
        {
            const int kk = chunk * GBK;
            #pragma unroll
            for (int it = 0; it < 4; it++) {
                int i = tid + it * 256;
                int row = i >> 3, seg = i & 7;
                int off = row * GSTRIDE + seg * 8;
                *(uint4*)&sB[off] = *(const uint4*)(g_wT + (size_t)(bn + row) * IN_DIM + kk + seg * 8);
            }
        }
        __syncthreads();

        // ---- issue next chunk's A loads (overlap with MMA below) ----
        if (chunk + 1 < NCHUNK) {
            const int kk = (chunk + 1) * GBK;
            #pragma unroll
            for (int it = 0; it < 8; it++) {
                int grow = bm + a_ld_row + it * 16;
                pref[it] = make_float4(0.f, 0.f, 0.f, 0.f);
                if (grow < M)
                    pref[it] = *(const float4*)(x + (size_t)grow * IN_DIM + kk + a_ld_f4 * 4);
            }
        }

        #pragma unroll
        for (int ks = 0; ks < 4; ks++) {
            const int k0 = ks * 16;
            uint32_t ah[2][4];
            #pragma unroll
            for (int mt = 0; mt < 2; mt++) {
                uint32_t eoff = (uint32_t)((wm + mt * 16 + a_row) * GSTRIDE + k0 + a_koff) * 2u;
                ldmx4(ah[mt][0], ah[mt][1], ah[mt][2], ah[mt][3], sA_b + eoff);
            }
            #pragma unroll
            for (int nt2 = 0; nt2 < 4; nt2++) {
                uint32_t eoff = (uint32_t)((wn + nt2 * 16 + b_row) * GSTRIDE + k0 + b_koff) * 2u;
                uint32_t bh[4];
                ldmx4(bh[0], bh[1], bh[2], bh[3], sB_b + eoff);
                #pragma unroll
                for (int mt = 0; mt < 2; mt++) {
                    #pragma unroll
                    for (int j = 0; j < 2; j++)
                        mma_f16(acc[mt][nt2 * 2 + j], ah[mt], &bh[j * 2]);
                }
            }
        }
        __syncthreads();
    }

    // ---- epilogue: tanh -> fp16 ----
    const int act = act_ptr ? act_ptr[0] : 1;
    #pragma unroll
    for (int mt = 0; mt < 2; mt++) {
        int r0 = bm + wm + mt * 16 + (lane >> 2);
        #pragma unroll
        for (int nt = 0; nt < 8; nt++) {
            int col = bn + wn + nt * 8 + (lane & 3) * 2;
            float c0 = acc[mt][nt][0], c1 = acc[mt][nt][1];
            float c2 = acc[mt][nt][2], c3 = acc[mt][nt][3];
            if (act) { c0 = tanhf(c0); c1 = tanhf(c1); c2 = tanhf(c2); c3 = tanhf(c3); }
            if (r0 < M)
                *(__half2*)(g_support_h + (size_t)r0 * OUT_DIM + col) = __floats2half2_rn(c0, c1);
            if (r0 + 8 < M)
                *(__half2*)(g_support_h + (size_t)(r0 + 8) * OUT_DIM + col) = __floats2half2_rn(c2, c3);
        }
    }
}

// ======================= CSR build =======================
__global__ void zero_counts(int N) {
    int i = blockIdx.x * blockDim.x + threadIdx.x;
    if (i < N) g_count[i] = 0;
}

__global__ void hist_kernel(const int* __restrict__ rows, int E) {
    int i4 = (blockIdx.x * blockDim.x + threadIdx.x) * 4;
    if (i4 + 3 < E) {
        int4 r = *(const int4*)(rows + i4);
        atomicAdd(&g_count[r.x], 1);
        atomicAdd(&g_count[r.y], 1);
        atomicAdd(&g_count[r.z], 1);
        atomicAdd(&g_count[r.w], 1);
    } else {
        for (int j = i4; j < E; j++) atomicAdd(&g_count[rows[j]], 1);
    }
}

// -- parallel scan, 3 phases, 1024 counts per block --
__global__ __launch_bounds__(1024) void scan_phase1(int N) {
    __shared__ int ws[32];
    int b = blockIdx.x, tid = threadIdx.x, lane = tid & 31, wid = tid >> 5;
    int i = b * 1024 + tid;
    int v = (i < N) ? g_count[i] : 0;
    #pragma unroll
    for (int o = 16; o > 0; o >>= 1) v += __shfl_down_sync(0xFFFFFFFFu, v, o);
    if (lane == 0) ws[wid] = v;
    __syncthreads();
    if (wid == 0) {
        int s = ws[lane];
        #pragma unroll
        for (int o = 16; o > 0; o >>= 1) s += __shfl_down_sync(0xFFFFFFFFu, s, o);
        if (lane == 0) g_blocksum[b] = s;
    }
}

__global__ __launch_bounds__(128) void scan_phase2(int NB) {
    __shared__ int ws[4];
    int tid = threadIdx.x, lane = tid & 31, wid = tid >> 5;
    int v = (tid < NB) ? g_blocksum[tid] : 0;
    int xv = v;
    #pragma unroll
    for (int o = 1; o < 32; o <<= 1) {
        int t = __shfl_up_sync(0xFFFFFFFFu, xv, o);
        if (lane >= o) xv += t;
    }
    if (lane == 31) ws[wid] = xv;
    __syncthreads();
    int carry = 0;
    #pragma unroll
    for (int w = 0; w < 4; w++) { if (w < wid) carry += ws[w]; }
    if (tid < NB) g_blockoff[tid] = carry + xv - v;   // exclusive
}

__global__ __launch_bounds__(1024) void scan_phase3(int N, int E) {
    __shared__ int ws[32];
    int b = blockIdx.x, tid = threadIdx.x, lane = tid & 31, wid = tid >> 5;
    int i = b * 1024 + tid;
    int v = (i < N) ? g_count[i] : 0;
    int xv = v;
    #pragma unroll
    for (int o = 1; o < 32; o <<= 1) {
        int t = __shfl_up_sync(0xFFFFFFFFu, xv, o);
        if (lane >= o) xv += t;
    }
    if (lane == 31) ws[wid] = xv;
    __syncthreads();
    if (wid == 0) {
        int wv = ws[lane];
        int y = wv;
        #pragma unroll
        for (int o = 1; o < 32; o <<= 1) {
            int t = __shfl_up_sync(0xFFFFFFFFu, y, o);
            if (lane >= o) y += t;
        }
        ws[lane] = y - wv;   // exclusive warp offsets
    }
    __syncthreads();
    int off = g_blockoff[b] + ws[wid] + xv - v;   // global exclusive prefix
    if (i < N) { g_rowstart[i] = off; g_cursor[i] = off; }
    if (i == N - 1) g_rowstart[N] = off + v;      // == E
}

__global__ void scatter_kernel(const int* __restrict__ rows,
                               const int* __restrict__ cols,
                               const float* __restrict__ vals, int E) {
    int i4 = (blockIdx.x * blockDim.x + threadIdx.x) * 4;
    if (i4 + 3 < E) {
        int4   r = *(const int4*)(rows + i4);
        int4   c = *(const int4*)(cols + i4);
        float4 v = *(const float4*)(vals + i4);
        int p0 = atomicAdd(&g_cursor[r.x], 1);
        g_edge[p0] = make_int2(c.x, __float_as_int(v.x));
        int p1 = atomicAdd(&g_cursor[r.y], 1);
        g_edge[p1] = make_int2(c.y, __float_as_int(v.y));
        int p2 = atomicAdd(&g_cursor[r.z], 1);
        g_edge[p2] = make_int2(c.z, __float_as_int(v.z));
        int p3 = atomicAdd(&g_cursor[r.w], 1);
        g_edge[p3] = make_int2(c.w, __float_as_int(v.w));
    } else {
        for (int j = i4; j < E; j++) {
            int p = atomicAdd(&g_cursor[rows[j]], 1);
            g_edge[p] = make_int2(cols[j], __float_as_int(vals[j]));
        }
    }
}

// ======================= SpMM half (128 output cols), warp per row, MLP=4 =======================
__global__ __launch_bounds__(256)
void spmm_half_kernel(float* __restrict__ out, int N, int colbase) {
    int wrow = (blockIdx.x * blockDim.x + threadIdx.x) >> 5;
    int lane = threadIdx.x & 31;
    if (wrow >= N) return;
    int s = g_rowstart[wrow];
    int e = g_rowstart[wrow + 1];
    float a0 = 0.f, a1 = 0.f, a2 = 0.f, a3 = 0.f;
    const size_t loff = (size_t)colbase + lane * 4;
    int i = s;
    for (; i + 4 <= e; i += 4) {
        int2 e0 = g_edge[i],     e1 = g_edge[i + 1];
        int2 e2 = g_edge[i + 2], e3 = g_edge[i + 3];
        uint2 q0 = *(const uint2*)(g_support_h + (size_t)e0.x * OUT_DIM + loff);
        uint2 q1 = *(const uint2*)(g_support_h + (size_t)e1.x * OUT_DIM + loff);
        uint2 q2 = *(const uint2*)(g_support_h + (size_t)e2.x * OUT_DIM + loff);
        uint2 q3 = *(const uint2*)(g_support_h + (size_t)e3.x * OUT_DIM + loff);
        float v0 = __int_as_float(e0.y), v1 = __int_as_float(e1.y);
        float v2 = __int_as_float(e2.y), v3 = __int_as_float(e3.y);
        {
            float2 f0 = __half22float2(*(const __half2*)&q0.x);
            float2 f1 = __half22float2(*(const __half2*)&q0.y);
            a0 += v0 * f0.x; a1 += v0 * f0.y; a2 += v0 * f1.x; a3 += v0 * f1.y;
        }
        {
            float2 f0 = __half22float2(*(const __half2*)&q1.x);
            float2 f1 = __half22float2(*(const __half2*)&q1.y);
            a0 += v1 * f0.x; a1 += v1 * f0.y; a2 += v1 * f1.x; a3 += v1 * f1.y;
        }
        {
            float2 f0 = __half22float2(*(const __half2*)&q2.x);
            float2 f1 = __half22float2(*(const __half2*)&q2.y);
            a0 += v2 * f0.x; a1 += v2 * f0.y; a2 += v2 * f1.x; a3 += v2 * f1.y;
        }
        {
            float2 f0 = __half22float2(*(const __half2*)&q3.x);
            float2 f1 = __half22float2(*(const __half2*)&q3.y);
            a0 += v3 * f0.x; a1 += v3 * f0.y; a2 += v3 * f1.x; a3 += v3 * f1.y;
        }
    }
    for (; i < e; i++) {
        int2 ed = g_edge[i];
        float v = __int_as_float(ed.y);
        uint2 q = *(const uint2*)(g_support_h + (size_t)ed.x * OUT_DIM + loff);
        float2 f0 = __half22float2(*(const __half2*)&q.x);
        float2 f1 = __half22float2(*(const __half2*)&q.y);
        a0 += v * f0.x; a1 += v * f0.y; a2 += v * f1.x; a3 += v * f1.y;
    }
    *(float4*)(out + (size_t)wrow * OUT_DIM + loff) = make_float4(a0, a1, a2, a3);
}

// ======================= launch =======================
extern "C" void kernel_launch(void* const* d_in, const int* in_sizes, int n_in,
                              void* d_out, int out_size) {
    const float* x    = (const float*)d_in[0];
    const float* w    = (const float*)d_in[1];
    const int*   erow = (const int*)d_in[2];
    const int*   ecol = (const int*)d_in[3];
    const float* eval = (const float*)d_in[4];
    const int*   act  = (n_in > 5) ? (const int*)d_in[5] : nullptr;

    int M = in_sizes[0] / IN_DIM;   // 100000
    int E = in_sizes[2];            // 3200000
    float* out = (float*)d_out;

    // ---- fork ----
    cudaEventRecord(g_evFork, 0);
    cudaStreamWaitEvent(g_sB, g_evFork, 0);

    // stream 0: convw -> gemm half 0 -> gemm half 1
    convw_kernel<<<(IN_DIM * OUT_DIM + 255) / 256, 256>>>(w);
    int gtiles = (M + 127) / 128;
    gemm_mma_kernel<<<gtiles, 256>>>(x, act, M, 0);
    cudaEventRecord(g_evG0, 0);
    gemm_mma_kernel<<<gtiles, 256>>>(x, act, M, 128);

    // stream B: CSR chain
    zero_counts<<<(M + 255) / 256, 256, 0, g_sB>>>(M);
    hist_kernel<<<(E / 4 + 255) / 256, 256, 0, g_sB>>>(erow, E);
    int NB = (M + 1023) / 1024;     // 98
    scan_phase1<<<NB, 1024, 0, g_sB>>>(M);
    scan_phase2<<<1, 128, 0, g_sB>>>(NB);
    scan_phase3<<<NB, 1024, 0, g_sB>>>(M, E);
    scatter_kernel<<<(E / 4 + 255) / 256, 256, 0, g_sB>>>(erow, ecol, eval, E);
    cudaEventRecord(g_evScat, g_sB);

    // stream B: spmm half 0 (needs gemm0 + scatter) — overlaps gemm half 1
    cudaStreamWaitEvent(g_sB, g_evG0, 0);
    long long spmm_threads = (long long)M * 32;
    unsigned spmm_blocks = (unsigned)((spmm_threads + 255) / 256);
    spmm_half_kernel<<<spmm_blocks, 256, 0, g_sB>>>(out, M, 0);
    cudaEventRecord(g_evS0, g_sB);

    // stream 0: spmm half 1 (needs gemm1 + scatter), then join
    cudaStreamWaitEvent(0, g_evScat, 0);
    spmm_half_kernel<<<spmm_blocks, 256>>>(out, M, 128);
    cudaStreamWaitEvent(0, g_evS0, 0);
}

// round 12
// speedup vs baseline: 3.3645x; 1.3559x over previous
#include <cuda_runtime.h>
#include <cuda_fp16.h>
#include <cuda_bf16.h>
#include <cstdint>

#define MAXN 100000
#define MAXE 3200000
#define IN_DIM 512
#define OUT_DIM 256

// ---------------- scratch (static __device__, no runtime allocation) ----------------
__device__ __half g_xh[(size_t)MAXN * IN_DIM];           // x in fp16, 102.4 MB
__device__ __half g_support_h[(size_t)MAXN * OUT_DIM];   // tanh(x@W) in fp16, 51.2 MB
__device__ __half g_wT[(size_t)OUT_DIM * IN_DIM];        // W^T fp16 [256][512]
__device__ int   g_count[MAXN];
__device__ int   g_rowstart[MAXN + 1];
__device__ int   g_cursor[MAXN];
__device__ int2  g_edge[MAXE];          // packed (col, val-bits)
__device__ int   g_blocksum[128];
__device__ int   g_blockoff[128];

// ---------------- host-side stream/event objects (created at load, before capture) ----------------
static cudaStream_t g_sB;
static cudaEvent_t  g_evFork, g_evG0, g_evScat, g_evS0;
struct _InitStreams {
    _InitStreams() {
        cudaStreamCreate(&g_sB);
        cudaEventCreateWithFlags(&g_evFork, cudaEventDisableTiming);
        cudaEventCreateWithFlags(&g_evG0,   cudaEventDisableTiming);
        cudaEventCreateWithFlags(&g_evScat, cudaEventDisableTiming);
        cudaEventCreateWithFlags(&g_evS0,   cudaEventDisableTiming);
    }
};
static _InitStreams g_init_streams;

// ======================= helpers =======================
__device__ __forceinline__ uint32_t smem_u32(const void* p) {
    uint32_t a;
    asm("{ .reg .u64 t; cvta.to.shared.u64 t, %1; cvt.u32.u64 %0, t; }" : "=r"(a) : "l"(p));
    return a;
}

__device__ __forceinline__ void ldmx4(uint32_t& r0, uint32_t& r1, uint32_t& r2, uint32_t& r3,
                                      uint32_t addr) {
    asm volatile("ldmatrix.sync.aligned.m8n8.x4.shared.b16 {%0,%1,%2,%3}, [%4];"
                 : "=r"(r0), "=r"(r1), "=r"(r2), "=r"(r3) : "r"(addr));
}

__device__ __forceinline__ void mma_f16(float* c, const uint32_t* a, const uint32_t* b) {
    asm volatile(
        "mma.sync.aligned.m16n8k16.row.col.f32.f16.f16.f32 "
        "{%0,%1,%2,%3}, {%4,%5,%6,%7}, {%8,%9}, {%0,%1,%2,%3};"
        : "+f"(c[0]), "+f"(c[1]), "+f"(c[2]), "+f"(c[3])
        : "r"(a[0]), "r"(a[1]), "r"(a[2]), "r"(a[3]), "r"(b[0]), "r"(b[1]));
}

// ======================= x -> fp16 (one pass, streaming) =======================
__global__ void convx_kernel(const float* __restrict__ x, long long total8) {
    long long i = (long long)blockIdx.x * blockDim.x + threadIdx.x;   // 8 floats per thread
    if (i >= total8) return;
    const float4* src = (const float4*)x + i * 2;
    float4 v0 = __ldcs(src);
    float4 v1 = __ldcs(src + 1);
    __half2 h0 = __floats2half2_rn(v0.x, v0.y);
    __half2 h1 = __floats2half2_rn(v0.z, v0.w);
    __half2 h2 = __floats2half2_rn(v1.x, v1.y);
    __half2 h3 = __floats2half2_rn(v1.z, v1.w);
    uint4 o = make_uint4(*(uint32_t*)&h0, *(uint32_t*)&h1, *(uint32_t*)&h2, *(uint32_t*)&h3);
    *((uint4*)g_xh + i) = o;
}

// ======================= W transpose -> fp16 =======================
__global__ void convw_kernel(const float* __restrict__ w) {
    int idx = blockIdx.x * blockDim.x + threadIdx.x;   // over 512*256
    if (idx >= IN_DIM * OUT_DIM) return;
    int k = idx / OUT_DIM, n = idx % OUT_DIM;
    g_wT[(size_t)n * IN_DIM + k] = __float2half_rn(w[idx]);
}

// ======================= fp16 HMMA GEMM + tanh -> fp16 =======================
// CTA tile 128(M) x 128(N), BK=64, 8 warps in 4x2 (warp tile 32x64).
// SMEM rows padded to 72 halfs (144 B) -> conflict-free ldmatrix.
// N half selected via n_base (two launches). A tile register-prefetched from fp16 g_xh.
#define GBK 64
#define GSTRIDE 72
#define NCHUNK (IN_DIM / GBK)   // 8

__global__ __launch_bounds__(256)
void gemm_mma_kernel(const int* __restrict__ act_ptr, int M, int n_base)
{
    __shared__ __align__(16) __half sA[128 * GSTRIDE];   // 18 KB
    __shared__ __align__(16) __half sB[128 * GSTRIDE];   // 18 KB

    const int tid = threadIdx.x;
    const int lane = tid & 31, wid = tid >> 5;
    const int bm = blockIdx.x * 128;
    const int bn = n_base;
    const int wm = (wid & 3) * 32;    // warp M offset
    const int wn = (wid >> 2) * 64;   // warp N offset

    const uint32_t sA_b = smem_u32(sA);
    const uint32_t sB_b = smem_u32(sB);

    float acc[2][8][4];
    #pragma unroll
    for (int i = 0; i < 2; i++)
        #pragma unroll
        for (int j = 0; j < 8; j++)
            #pragma unroll
            for (int q = 0; q < 4; q++) acc[i][j][q] = 0.f;

    // A tile: 128 rows x 64 halfs = 128 B/row = 8 uint4/row -> 1024 uint4, 4/thread
    const int a_ld_row = tid >> 3;    // 0..31, rows step by 32 per it
    const int a_ld_seg = tid & 7;     // 0..7
    // ldmatrix lane addressing
    const int a_row = (lane & 15), a_koff = (lane >> 4) * 8;
    const int b_row = (lane & 7) + ((lane >> 4) & 1) * 8, b_koff = ((lane >> 3) & 1) * 8;

    const uint4 zero4 = make_uint4(0u, 0u, 0u, 0u);

    // ---- prefetch chunk 0 A (fp16, streaming) ----
    uint4 pref[4];
    #pragma unroll
    for (int it = 0; it < 4; it++) {
        int grow = bm + a_ld_row + it * 32;
        pref[it] = (grow < M)
            ? __ldcs((const uint4*)(g_xh + (size_t)grow * IN_DIM + a_ld_seg * 8))
            : zero4;
    }

    for (int chunk = 0; chunk < NCHUNK; chunk++) {
        // ---- store prefetched A ----
        #pragma unroll
        for (int it = 0; it < 4; it++) {
            int off = (a_ld_row + it * 32) * GSTRIDE + a_ld_seg * 8;
            *(uint4*)&sA[off] = pref[it];
        }
        // ---- B tile (L2-resident W^T fp16): 128 rows x 64 halfs = 1024 uint4, 4/thread ----
        {
            const int kk = chunk * GBK;
            #pragma unroll
            for (int it = 0; it < 4; it++) {
                int i = tid + it * 256;
                int row = i >> 3, seg = i & 7;
                int off = row * GSTRIDE + seg * 8;
                *(uint4*)&sB[off] = *(const uint4*)(g_wT + (size_t)(bn + row) * IN_DIM + kk + seg * 8);
            }
        }
        __syncthreads();

        // ---- issue next chunk's A loads (overlap with MMA below) ----
        if (chunk + 1 < NCHUNK) {
            const int kk = (chunk + 1) * GBK;
            #pragma unroll
            for (int it = 0; it < 4; it++) {
                int grow = bm + a_ld_row + it * 32;
                pref[it] = (grow < M)
                    ? __ldcs((const uint4*)(g_xh + (size_t)grow * IN_DIM + kk + a_ld_seg * 8))
                    : zero4;
            }
        }

        #pragma unroll
        for (int ks = 0; ks < 4; ks++) {
            const int k0 = ks * 16;
            uint32_t ah[2][4];
            #pragma unroll
            for (int mt = 0; mt < 2; mt++) {
                uint32_t eoff = (uint32_t)((wm + mt * 16 + a_row) * GSTRIDE + k0 + a_koff) * 2u;
                ldmx4(ah[mt][0], ah[mt][1], ah[mt][2], ah[mt][3], sA_b + eoff);
            }
            #pragma unroll
            for (int nt2 = 0; nt2 < 4; nt2++) {
                uint32_t eoff = (uint32_t)((wn + nt2 * 16 + b_row) * GSTRIDE + k0 + b_koff) * 2u;
                uint32_t bh[4];
                ldmx4(bh[0], bh[1], bh[2], bh[3], sB_b + eoff);
                #pragma unroll
                for (int mt = 0; mt < 2; mt++) {
                    #pragma unroll
                    for (int j = 0; j < 2; j++)
                        mma_f16(acc[mt][nt2 * 2 + j], ah[mt], &bh[j * 2]);
                }
            }
        }
        __syncthreads();
    }

    // ---- epilogue: tanh -> fp16 (default policy: keep support resident in L2) ----
    const int act = act_ptr ? act_ptr[0] : 1;
    #pragma unroll
    for (int mt = 0; mt < 2; mt++) {
        int r0 = bm + wm + mt * 16 + (lane >> 2);
        #pragma unroll
        for (int nt = 0; nt < 8; nt++) {
            int col = bn + wn + nt * 8 + (lane & 3) * 2;
            float c0 = acc[mt][nt][0], c1 = acc[mt][nt][1];
            float c2 = acc[mt][nt][2], c3 = acc[mt][nt][3];
            if (act) { c0 = tanhf(c0); c1 = tanhf(c1); c2 = tanhf(c2); c3 = tanhf(c3); }
            if (r0 < M)
                *(__half2*)(g_support_h + (size_t)r0 * OUT_DIM + col) = __floats2half2_rn(c0, c1);
            if (r0 + 8 < M)
                *(__half2*)(g_support_h + (size_t)(r0 + 8) * OUT_DIM + col) = __floats2half2_rn(c2, c3);
        }
    }
}

// ======================= CSR build =======================
__global__ void zero_counts(int N) {
    int i = blockIdx.x * blockDim.x + threadIdx.x;
    if (i < N) g_count[i] = 0;
}

__global__ void hist_kernel(const int* __restrict__ rows, int E) {
    int i4 = (blockIdx.x * blockDim.x + threadIdx.x) * 4;
    if (i4 + 3 < E) {
        int4 r = __ldcs((const int4*)(rows + i4));
        atomicAdd(&g_count[r.x], 1);
        atomicAdd(&g_count[r.y], 1);
        atomicAdd(&g_count[r.z], 1);
        atomicAdd(&g_count[r.w], 1);
    } else {
        for (int j = i4; j < E; j++) atomicAdd(&g_count[rows[j]], 1);
    }
}

// -- parallel scan, 3 phases, 1024 counts per block --
__global__ __launch_bounds__(1024) void scan_phase1(int N) {
    __shared__ int ws[32];
    int b = blockIdx.x, tid = threadIdx.x, lane = tid & 31, wid = tid >> 5;
    int i = b * 1024 + tid;
    int v = (i < N) ? g_count[i] : 0;
    #pragma unroll
    for (int o = 16; o > 0; o >>= 1) v += __shfl_down_sync(0xFFFFFFFFu, v, o);
    if (lane == 0) ws[wid] = v;
    __syncthreads();
    if (wid == 0) {
        int s = ws[lane];
        #pragma unroll
        for (int o = 16; o > 0; o >>= 1) s += __shfl_down_sync(0xFFFFFFFFu, s, o);
        if (lane == 0) g_blocksum[b] = s;
    }
}

__global__ __launch_bounds__(128) void scan_phase2(int NB) {
    __shared__ int ws[4];
    int tid = threadIdx.x, lane = tid & 31, wid = tid >> 5;
    int v = (tid < NB) ? g_blocksum[tid] : 0;
    int xv = v;
    #pragma unroll
    for (int o = 1; o < 32; o <<= 1) {
        int t = __shfl_up_sync(0xFFFFFFFFu, xv, o);
        if (lane >= o) xv += t;
    }
    if (lane == 31) ws[wid] = xv;
    __syncthreads();
    int carry = 0;
    #pragma unroll
    for (int w = 0; w < 4; w++) { if (w < wid) carry += ws[w]; }
    if (tid < NB) g_blockoff[tid] = carry + xv - v;   // exclusive
}

__global__ __launch_bounds__(1024) void scan_phase3(int N, int E) {
    __shared__ int ws[32];
    int b = blockIdx.x, tid = threadIdx.x, lane = tid & 31, wid = tid >> 5;
    int i = b * 1024 + tid;
    int v = (i < N) ? g_count[i] : 0;
    int xv = v;
    #pragma unroll
    for (int o = 1; o < 32; o <<= 1) {
        int t = __shfl_up_sync(0xFFFFFFFFu, xv, o);
        if (lane >= o) xv += t;
    }
    if (lane == 31) ws[wid] = xv;
    __syncthreads();
    if (wid == 0) {
        int wv = ws[lane];
        int y = wv;
        #pragma unroll
        for (int o = 1; o < 32; o <<= 1) {
            int t = __shfl_up_sync(0xFFFFFFFFu, y, o);
            if (lane >= o) y += t;
        }
        ws[lane] = y - wv;   // exclusive warp offsets
    }
    __syncthreads();
    int off = g_blockoff[b] + ws[wid] + xv - v;   // global exclusive prefix
    if (i < N) { g_rowstart[i] = off; g_cursor[i] = off; }
    if (i == N - 1) g_rowstart[N] = off + v;      // == E
}

__global__ void scatter_kernel(const int* __restrict__ rows,
                               const int* __restrict__ cols,
                               const float* __restrict__ vals, int E) {
    int i4 = (blockIdx.x * blockDim.x + threadIdx.x) * 4;
    if (i4 + 3 < E) {
        int4   r = __ldcs((const int4*)(rows + i4));
        int4   c = __ldcs((const int4*)(cols + i4));
        float4 v = __ldcs((const float4*)(vals + i4));
        int p0 = atomicAdd(&g_cursor[r.x], 1);
        g_edge[p0] = make_int2(c.x, __float_as_int(v.x));
        int p1 = atomicAdd(&g_cursor[r.y], 1);
        g_edge[p1] = make_int2(c.y, __float_as_int(v.y));
        int p2 = atomicAdd(&g_cursor[r.z], 1);
        g_edge[p2] = make_int2(c.z, __float_as_int(v.z));
        int p3 = atomicAdd(&g_cursor[r.w], 1);
        g_edge[p3] = make_int2(c.w, __float_as_int(v.w));
    } else {
        for (int j = i4; j < E; j++) {
            int p = atomicAdd(&g_cursor[rows[j]], 1);
            g_edge[p] = make_int2(cols[j], __float_as_int(vals[j]));
        }
    }
}

// ======================= SpMM half (128 output cols), warp per row, MLP=4 =======================
__global__ __launch_bounds__(256)
void spmm_half_kernel(float* __restrict__ out, int N, int colbase) {
    int wrow = (blockIdx.x * blockDim.x + threadIdx.x) >> 5;
    int lane = threadIdx.x & 31;
    if (wrow >= N) return;
    int s = g_rowstart[wrow];
    int e = g_rowstart[wrow + 1];
    float a0 = 0.f, a1 = 0.f, a2 = 0.f, a3 = 0.f;
    const size_t loff = (size_t)colbase + lane * 4;
    int i = s;
    for (; i + 4 <= e; i += 4) {
        int2 e0 = g_edge[i],     e1 = g_edge[i + 1];
        int2 e2 = g_edge[i + 2], e3 = g_edge[i + 3];
        uint2 q0 = *(const uint2*)(g_support_h + (size_t)e0.x * OUT_DIM + loff);
        uint2 q1 = *(const uint2*)(g_support_h + (size_t)e1.x * OUT_DIM + loff);
        uint2 q2 = *(const uint2*)(g_support_h + (size_t)e2.x * OUT_DIM + loff);
        uint2 q3 = *(const uint2*)(g_support_h + (size_t)e3.x * OUT_DIM + loff);
        float v0 = __int_as_float(e0.y), v1 = __int_as_float(e1.y);
        float v2 = __int_as_float(e2.y), v3 = __int_as_float(e3.y);
        {
            float2 f0 = __half22float2(*(const __half2*)&q0.x);
            float2 f1 = __half22float2(*(const __half2*)&q0.y);
            a0 += v0 * f0.x; a1 += v0 * f0.y; a2 += v0 * f1.x; a3 += v0 * f1.y;
        }
        {
            float2 f0 = __half22float2(*(const __half2*)&q1.x);
            float2 f1 = __half22float2(*(const __half2*)&q1.y);
            a0 += v1 * f0.x; a1 += v1 * f0.y; a2 += v1 * f1.x; a3 += v1 * f1.y;
        }
        {
            float2 f0 = __half22float2(*(const __half2*)&q2.x);
            float2 f1 = __half22float2(*(const __half2*)&q2.y);
            a0 += v2 * f0.x; a1 += v2 * f0.y; a2 += v2 * f1.x; a3 += v2 * f1.y;
        }
        {
            float2 f0 = __half22float2(*(const __half2*)&q3.x);
            float2 f1 = __half22float2(*(const __half2*)&q3.y);
            a0 += v3 * f0.x; a1 += v3 * f0.y; a2 += v3 * f1.x; a3 += v3 * f1.y;
        }
    }
    for (; i < e; i++) {
        int2 ed = g_edge[i];
        float v = __int_as_float(ed.y);
        uint2 q = *(const uint2*)(g_support_h + (size_t)ed.x * OUT_DIM + loff);
        float2 f0 = __half22float2(*(const __half2*)&q.x);
        float2 f1 = __half22float2(*(const __half2*)&q.y);
        a0 += v * f0.x; a1 += v * f0.y; a2 += v * f1.x; a3 += v * f1.y;
    }
    __stcs((float4*)(out + (size_t)wrow * OUT_DIM + loff), make_float4(a0, a1, a2, a3));
}

// ======================= launch =======================
extern "C" void kernel_launch(void* const* d_in, const int* in_sizes, int n_in,
                              void* d_out, int out_size) {
    const float* x    = (const float*)d_in[0];
    const float* w    = (const float*)d_in[1];
    const int*   erow = (const int*)d_in[2];
    const int*   ecol = (const int*)d_in[3];
    const float* eval = (const float*)d_in[4];
    const int*   act  = (n_in > 5) ? (const int*)d_in[5] : nullptr;

    int M = in_sizes[0] / IN_DIM;   // 100000
    int E = in_sizes[2];            // 3200000
    float* out = (float*)d_out;

    // ---- fork ----
    cudaEventRecord(g_evFork, 0);
    cudaStreamWaitEvent(g_sB, g_evFork, 0);

    // stream 0: convw -> convx -> gemm half 0 -> gemm half 1
    convw_kernel<<<(IN_DIM * OUT_DIM + 255) / 256, 256>>>(w);
    long long total8 = (long long)M * IN_DIM / 8;
    convx_kernel<<<(unsigned)((total8 + 255) / 256), 256>>>(x, total8);
    int gtiles = (M + 127) / 128;
    gemm_mma_kernel<<<gtiles, 256>>>(act, M, 0);
    cudaEventRecord(g_evG0, 0);
    gemm_mma_kernel<<<gtiles, 256>>>(act, M, 128);

    // stream B: CSR chain
    zero_counts<<<(M + 255) / 256, 256, 0, g_sB>>>(M);
    hist_kernel<<<(E / 4 + 255) / 256, 256, 0, g_sB>>>(erow, E);
    int NB = (M + 1023) / 1024;     // 98
    scan_phase1<<<NB, 1024, 0, g_sB>>>(M);
    scan_phase2<<<1, 128, 0, g_sB>>>(NB);
    scan_phase3<<<NB, 1024, 0, g_sB>>>(M, E);
    scatter_kernel<<<(E / 4 + 255) / 256, 256, 0, g_sB>>>(erow, ecol, eval, E);
    cudaEventRecord(g_evScat, g_sB);

    // stream B: spmm half 0 (needs gemm0 + scatter) — overlaps gemm half 1
    cudaStreamWaitEvent(g_sB, g_evG0, 0);
    long long spmm_threads = (long long)M * 32;
    unsigned spmm_blocks = (unsigned)((spmm_threads + 255) / 256);
    spmm_half_kernel<<<spmm_blocks, 256, 0, g_sB>>>(out, M, 0);
    cudaEventRecord(g_evS0, g_sB);

    // stream 0: spmm half 1 (needs gemm1 + scatter), then join
    cudaStreamWaitEvent(0, g_evScat, 0);
    spmm_half_kernel<<<spmm_blocks, 256>>>(out, M, 128);
    cudaStreamWaitEvent(0, g_evS0, 0);
}

// round 13
// speedup vs baseline: 3.3752x; 1.0032x over previous
#include <cuda_runtime.h>
#include <cuda_fp16.h>
#include <cuda_bf16.h>
#include <cstdint>

#define MAXN 100000
#define MAXE 3200000
#define IN_DIM 512
#define OUT_DIM 256

// ---------------- scratch (static __device__, no runtime allocation) ----------------
__device__ __half g_xh[(size_t)MAXN * IN_DIM];           // x in fp16, 102.4 MB
__device__ __half g_support_h[(size_t)MAXN * OUT_DIM];   // tanh(x@W) in fp16, 51.2 MB
__device__ __half g_wT[(size_t)OUT_DIM * IN_DIM];        // W^T fp16 [256][512]
__device__ int   g_count[MAXN];
__device__ int   g_rowstart[MAXN + 1];
__device__ int   g_cursor[MAXN];
__device__ int2  g_edge[MAXE];          // packed (col, val-bits)
__device__ int   g_blocksum[128];
__device__ int   g_blockoff[128];

// ======================= helpers =======================
__device__ __forceinline__ uint32_t smem_u32(const void* p) {
    uint32_t a;
    asm("{ .reg .u64 t; cvta.to.shared.u64 t, %1; cvt.u32.u64 %0, t; }" : "=r"(a) : "l"(p));
    return a;
}

__device__ __forceinline__ void ldmx4(uint32_t& r0, uint32_t& r1, uint32_t& r2, uint32_t& r3,
                                      uint32_t addr) {
    asm volatile("ldmatrix.sync.aligned.m8n8.x4.shared.b16 {%0,%1,%2,%3}, [%4];"
                 : "=r"(r0), "=r"(r1), "=r"(r2), "=r"(r3) : "r"(addr));
}

__device__ __forceinline__ void mma_f16(float* c, const uint32_t* a, const uint32_t* b) {
    asm volatile(
        "mma.sync.aligned.m16n8k16.row.col.f32.f16.f16.f32 "
        "{%0,%1,%2,%3}, {%4,%5,%6,%7}, {%8,%9}, {%0,%1,%2,%3};"
        : "+f"(c[0]), "+f"(c[1]), "+f"(c[2]), "+f"(c[3])
        : "r"(a[0]), "r"(a[1]), "r"(a[2]), "r"(a[3]), "r"(b[0]), "r"(b[1]));
}

__device__ __forceinline__ void cpa16(uint32_t dst, const void* src, int nbytes) {
    asm volatile("cp.async.cg.shared.global [%0], [%1], 16, %2;"
                 :: "r"(dst), "l"(src), "r"(nbytes));
}
#define CPA_COMMIT() asm volatile("cp.async.commit_group;" ::: "memory")
#define CPA_WAIT(n)  asm volatile("cp.async.wait_group %0;" :: "n"(n) : "memory")

// ======================= x -> fp16 (one pass, streaming) =======================
__global__ void convx_kernel(const float* __restrict__ x, long long total8) {
    long long i = (long long)blockIdx.x * blockDim.x + threadIdx.x;   // 8 floats per thread
    if (i >= total8) return;
    const float4* src = (const float4*)x + i * 2;
    float4 v0 = __ldcs(src);
    float4 v1 = __ldcs(src + 1);
    __half2 h0 = __floats2half2_rn(v0.x, v0.y);
    __half2 h1 = __floats2half2_rn(v0.z, v0.w);
    __half2 h2 = __floats2half2_rn(v1.x, v1.y);
    __half2 h3 = __floats2half2_rn(v1.z, v1.w);
    uint4 o = make_uint4(*(uint32_t*)&h0, *(uint32_t*)&h1, *(uint32_t*)&h2, *(uint32_t*)&h3);
    *((uint4*)g_xh + i) = o;
}

// ======================= W transpose -> fp16 =======================
__global__ void convw_kernel(const float* __restrict__ w) {
    int idx = blockIdx.x * blockDim.x + threadIdx.x;   // over 512*256
    if (idx >= IN_DIM * OUT_DIM) return;
    int k = idx / OUT_DIM, n = idx % OUT_DIM;
    g_wT[(size_t)n * IN_DIM + k] = __float2half_rn(w[idx]);
}

// ======================= fp16 HMMA GEMM, cp.async double-buffered =======================
// CTA tile 128(M) x 128(N), BK=64, 8 warps in 4x2 (warp tile 32x64).
// SMEM rows padded to 72 halfs (144 B, 16B-aligned) -> conflict-free ldmatrix.
// 2-stage ping-pong in dynamic SMEM: [A0 | B0 | A1 | B1], 18432 B each.
#define GBK 64
#define GSTRIDE 72
#define NCHUNK (IN_DIM / GBK)   // 8
#define TILE_B 18432            // 128 * 72 * 2 bytes
#define GSMEM_TOTAL (4 * TILE_B)

__global__ __launch_bounds__(256, 2)
void gemm_mma_kernel(const int* __restrict__ act_ptr, int M, int n_base)
{
    extern __shared__ __align__(16) char smem[];
    const uint32_t smem_b = smem_u32(smem);

    const int tid = threadIdx.x;
    const int lane = tid & 31, wid = tid >> 5;
    const int bm = blockIdx.x * 128;
    const int bn = n_base;
    const int wm = (wid & 3) * 32;    // warp M offset
    const int wn = (wid >> 2) * 64;   // warp N offset

    float acc[2][8][4];
    #pragma unroll
    for (int i = 0; i < 2; i++)
        #pragma unroll
        for (int j = 0; j < 8; j++)
            #pragma unroll
            for (int q = 0; q < 4; q++) acc[i][j][q] = 0.f;

    // load geometry: tiles are 128 rows x 64 halfs = 8 x 16B chunks per row,
    // 1024 chunks per tile, 4 per thread
    const int ld_row = tid >> 3;     // 0..31, rows step by 32
    const int ld_seg = tid & 7;      // 0..7
    // ldmatrix lane addressing
    const int a_row = (lane & 15), a_koff = (lane >> 4) * 8;
    const int b_row = (lane & 7) + ((lane >> 4) & 1) * 8, b_koff = ((lane >> 3) & 1) * 8;

    // ---- stage loader (cp.async, no registers) ----
    auto load_stage = [&](int chunk, int stage) {
        const int kk = chunk * GBK;
        const uint32_t aB = smem_b + stage * 2 * TILE_B;
        const uint32_t bB = aB + TILE_B;
        #pragma unroll
        for (int it = 0; it < 4; it++) {
            int row = ld_row + it * 32;
            int grow = bm + row;
            int ok = (grow < M);
            const __half* src = g_xh + (size_t)(ok ? grow : 0) * IN_DIM + kk + ld_seg * 8;
            cpa16(aB + (uint32_t)(row * GSTRIDE + ld_seg * 8) * 2u, src, ok ? 16 : 0);
        }
        #pragma unroll
        for (int it = 0; it < 4; it++) {
            int i = tid + it * 256;
            int row = i >> 3, seg = i & 7;
            const __half* src = g_wT + (size_t)(bn + row) * IN_DIM + kk + seg * 8;
            cpa16(bB + (uint32_t)(row * GSTRIDE + seg * 8) * 2u, src, 16);
        }
        CPA_COMMIT();
    };

    load_stage(0, 0);

    for (int chunk = 0; chunk < NCHUNK; chunk++) {
        if (chunk + 1 < NCHUNK) {
            load_stage(chunk + 1, (chunk + 1) & 1);
            CPA_WAIT(1);
        } else {
            CPA_WAIT(0);
        }
        __syncthreads();

        const uint32_t sA_b = smem_b + (chunk & 1) * 2 * TILE_B;
        const uint32_t sB_b = sA_b + TILE_B;

        #pragma unroll
        for (int ks = 0; ks < 4; ks++) {
            const int k0 = ks * 16;
            uint32_t ah[2][4];
            #pragma unroll
            for (int mt = 0; mt < 2; mt++) {
                uint32_t eoff = (uint32_t)((wm + mt * 16 + a_row) * GSTRIDE + k0 + a_koff) * 2u;
                ldmx4(ah[mt][0], ah[mt][1], ah[mt][2], ah[mt][3], sA_b + eoff);
            }
            #pragma unroll
            for (int nt2 = 0; nt2 < 4; nt2++) {
                uint32_t eoff = (uint32_t)((wn + nt2 * 16 + b_row) * GSTRIDE + k0 + b_koff) * 2u;
                uint32_t bh[4];
                ldmx4(bh[0], bh[1], bh[2], bh[3], sB_b + eoff);
                #pragma unroll
                for (int mt = 0; mt < 2; mt++) {
                    #pragma unroll
                    for (int j = 0; j < 2; j++)
                        mma_f16(acc[mt][nt2 * 2 + j], ah[mt], &bh[j * 2]);
                }
            }
        }
        __syncthreads();   // protect buffer before next-next stage overwrites
    }

    // ---- epilogue: tanh -> fp16 (default policy: keep support resident in L2) ----
    const int act = act_ptr ? act_ptr[0] : 1;
    #pragma unroll
    for (int mt = 0; mt < 2; mt++) {
        int r0 = bm + wm + mt * 16 + (lane >> 2);
        #pragma unroll
        for (int nt = 0; nt < 8; nt++) {
            int col = bn + wn + nt * 8 + (lane & 3) * 2;
            float c0 = acc[mt][nt][0], c1 = acc[mt][nt][1];
            float c2 = acc[mt][nt][2], c3 = acc[mt][nt][3];
            if (act) { c0 = tanhf(c0); c1 = tanhf(c1); c2 = tanhf(c2); c3 = tanhf(c3); }
            if (r0 < M)
                *(__half2*)(g_support_h + (size_t)r0 * OUT_DIM + col) = __floats2half2_rn(c0, c1);
            if (r0 + 8 < M)
                *(__half2*)(g_support_h + (size_t)(r0 + 8) * OUT_DIM + col) = __floats2half2_rn(c2, c3);
        }
    }
}

// ======================= CSR build =======================
__global__ void zero_counts(int N) {
    int i = blockIdx.x * blockDim.x + threadIdx.x;
    if (i < N) g_count[i] = 0;
}

__global__ void hist_kernel(const int* __restrict__ rows, int E) {
    int i4 = (blockIdx.x * blockDim.x + threadIdx.x) * 4;
    if (i4 + 3 < E) {
        int4 r = __ldcs((const int4*)(rows + i4));
        atomicAdd(&g_count[r.x], 1);
        atomicAdd(&g_count[r.y], 1);
        atomicAdd(&g_count[r.z], 1);
        atomicAdd(&g_count[r.w], 1);
    } else {
        for (int j = i4; j < E; j++) atomicAdd(&g_count[rows[j]], 1);
    }
}

// -- parallel scan, 3 phases, 1024 counts per block --
__global__ __launch_bounds__(1024) void scan_phase1(int N) {
    __shared__ int ws[32];
    int b = blockIdx.x, tid = threadIdx.x, lane = tid & 31, wid = tid >> 5;
    int i = b * 1024 + tid;
    int v = (i < N) ? g_count[i] : 0;
    #pragma unroll
    for (int o = 16; o > 0; o >>= 1) v += __shfl_down_sync(0xFFFFFFFFu, v, o);
    if (lane == 0) ws[wid] = v;
    __syncthreads();
    if (wid == 0) {
        int s = ws[lane];
        #pragma unroll
        for (int o = 16; o > 0; o >>= 1) s += __shfl_down_sync(0xFFFFFFFFu, s, o);
        if (lane == 0) g_blocksum[b] = s;
    }
}

__global__ __launch_bounds__(128) void scan_phase2(int NB) {
    __shared__ int ws[4];
    int tid = threadIdx.x, lane = tid & 31, wid = tid >> 5;
    int v = (tid < NB) ? g_blocksum[tid] : 0;
    int xv = v;
    #pragma unroll
    for (int o = 1; o < 32; o <<= 1) {
        int t = __shfl_up_sync(0xFFFFFFFFu, xv, o);
        if (lane >= o) xv += t;
    }
    if (lane == 31) ws[wid] = xv;
    __syncthreads();
    int carry = 0;
    #pragma unroll
    for (int w = 0; w < 4; w++) { if (w < wid) carry += ws[w]; }
    if (tid < NB) g_blockoff[tid] = carry + xv - v;   // exclusive
}

__global__ __launch_bounds__(1024) void scan_phase3(int N, int E) {
    __shared__ int ws[32];
    int b = blockIdx.x, tid = threadIdx.x, lane = tid & 31, wid = tid >> 5;
    int i = b * 1024 + tid;
    int v = (i < N) ? g_count[i] : 0;
    int xv = v;
    #pragma unroll
    for (int o = 1; o < 32; o <<= 1) {
        int t = __shfl_up_sync(0xFFFFFFFFu, xv, o);
        if (lane >= o) xv += t;
    }
    if (lane == 31) ws[wid] = xv;
    __syncthreads();
    if (wid == 0) {
        int wv = ws[lane];
        int y = wv;
        #pragma unroll
        for (int o = 1; o < 32; o <<= 1) {
            int t = __shfl_up_sync(0xFFFFFFFFu, y, o);
            if (lane >= o) y += t;
        }
        ws[lane] = y - wv;   // exclusive warp offsets
    }
    __syncthreads();
    int off = g_blockoff[b] + ws[wid] + xv - v;   // global exclusive prefix
    if (i < N) { g_rowstart[i] = off; g_cursor[i] = off; }
    if (i == N - 1) g_rowstart[N] = off + v;      // == E
}

__global__ void scatter_kernel(const int* __restrict__ rows,
                               const int* __restrict__ cols,
                               const float* __restrict__ vals, int E) {
    int i4 = (blockIdx.x * blockDim.x + threadIdx.x) * 4;
    if (i4 + 3 < E) {
        int4   r = __ldcs((const int4*)(rows + i4));
        int4   c = __ldcs((const int4*)(cols + i4));
        float4 v = __ldcs((const float4*)(vals + i4));
        int p0 = atomicAdd(&g_cursor[r.x], 1);
        g_edge[p0] = make_int2(c.x, __float_as_int(v.x));
        int p1 = atomicAdd(&g_cursor[r.y], 1);
        g_edge[p1] = make_int2(c.y, __float_as_int(v.y));
        int p2 = atomicAdd(&g_cursor[r.z], 1);
        g_edge[p2] = make_int2(c.z, __float_as_int(v.z));
        int p3 = atomicAdd(&g_cursor[r.w], 1);
        g_edge[p3] = make_int2(c.w, __float_as_int(v.w));
    } else {
        for (int j = i4; j < E; j++) {
            int p = atomicAdd(&g_cursor[rows[j]], 1);
            g_edge[p] = make_int2(cols[j], __float_as_int(vals[j]));
        }
    }
}

// ======================= SpMM half (128 output cols), warp per row, MLP=8 =======================
__global__ __launch_bounds__(256)
void spmm_half_kernel(float* __restrict__ out, int N, int colbase) {
    int wrow = (blockIdx.x * blockDim.x + threadIdx.x) >> 5;
    int lane = threadIdx.x & 31;
    if (wrow >= N) return;
    int s = g_rowstart[wrow];
    int e = g_rowstart[wrow + 1];
    float a0 = 0.f, a1 = 0.f, a2 = 0.f, a3 = 0.f;
    const size_t loff = (size_t)colbase + lane * 4;
    int i = s;
    for (; i + 8 <= e; i += 8) {
        int2 ed[8];
        uint2 q[8];
        #pragma unroll
        for (int u = 0; u < 8; u++) ed[u] = g_edge[i + u];
        #pragma unroll
        for (int u = 0; u < 8; u++)
            q[u] = *(const uint2*)(g_support_h + (size_t)ed[u].x * OUT_DIM + loff);
        #pragma unroll
        for (int u = 0; u < 8; u++) {
            float v = __int_as_float(ed[u].y);
            float2 f0 = __half22float2(*(const __half2*)&q[u].x);
            float2 f1 = __half22float2(*(const __half2*)&q[u].y);
            a0 += v * f0.x; a1 += v * f0.y; a2 += v * f1.x; a3 += v * f1.y;
        }
    }
    for (; i < e; i++) {
        int2 ed = g_edge[i];
        float v = __int_as_float(ed.y);
        uint2 q = *(const uint2*)(g_support_h + (size_t)ed.x * OUT_DIM + loff);
        float2 f0 = __half22float2(*(const __half2*)&q.x);
        float2 f1 = __half22float2(*(const __half2*)&q.y);
        a0 += v * f0.x; a1 += v * f0.y; a2 += v * f1.x; a3 += v * f1.y;
    }
    __stcs((float4*)(out + (size_t)wrow * OUT_DIM + loff), make_float4(a0, a1, a2, a3));
}

// ---------------- host-side stream/event objects + func attrs (at load, before capture) ----------------
static cudaStream_t g_sB;
static cudaEvent_t  g_evFork, g_evG0, g_evScat, g_evS0;
struct _InitStreams {
    _InitStreams() {
        cudaStreamCreate(&g_sB);
        cudaEventCreateWithFlags(&g_evFork, cudaEventDisableTiming);
        cudaEventCreateWithFlags(&g_evG0,   cudaEventDisableTiming);
        cudaEventCreateWithFlags(&g_evScat, cudaEventDisableTiming);
        cudaEventCreateWithFlags(&g_evS0,   cudaEventDisableTiming);
        cudaFuncSetAttribute(gemm_mma_kernel,
                             cudaFuncAttributeMaxDynamicSharedMemorySize, GSMEM_TOTAL);
    }
};
static _InitStreams g_init_streams;

// ======================= launch =======================
extern "C" void kernel_launch(void* const* d_in, const int* in_sizes, int n_in,
                              void* d_out, int out_size) {
    const float* x    = (const float*)d_in[0];
    const float* w    = (const float*)d_in[1];
    const int*   erow = (const int*)d_in[2];
    const int*   ecol = (const int*)d_in[3];
    const float* eval = (const float*)d_in[4];
    const int*   act  = (n_in > 5) ? (const int*)d_in[5] : nullptr;

    int M = in_sizes[0] / IN_DIM;   // 100000
    int E = in_sizes[2];            // 3200000
    float* out = (float*)d_out;

    // ---- fork ----
    cudaEventRecord(g_evFork, 0);
    cudaStreamWaitEvent(g_sB, g_evFork, 0);

    // stream 0: convw -> convx -> gemm half 0 -> gemm half 1
    convw_kernel<<<(IN_DIM * OUT_DIM + 255) / 256, 256>>>(w);
    long long total8 = (long long)M * IN_DIM / 8;
    convx_kernel<<<(unsigned)((total8 + 255) / 256), 256>>>(x, total8);
    int gtiles = (M + 127) / 128;
    gemm_mma_kernel<<<gtiles, 256, GSMEM_TOTAL>>>(act, M, 0);
    cudaEventRecord(g_evG0, 0);
    gemm_mma_kernel<<<gtiles, 256, GSMEM_TOTAL>>>(act, M, 128);

    // stream B: CSR chain
    zero_counts<<<(M + 255) / 256, 256, 0, g_sB>>>(M);
    hist_kernel<<<(E / 4 + 255) / 256, 256, 0, g_sB>>>(erow, E);
    int NB = (M + 1023) / 1024;     // 98
    scan_phase1<<<NB, 1024, 0, g_sB>>>(M);
    scan_phase2<<<1, 128, 0, g_sB>>>(NB);
    scan_phase3<<<NB, 1024, 0, g_sB>>>(M, E);
    scatter_kernel<<<(E / 4 + 255) / 256, 256, 0, g_sB>>>(erow, ecol, eval, E);
    cudaEventRecord(g_evScat, g_sB);

    // stream B: spmm half 0 (needs gemm0 + scatter) — overlaps gemm half 1
    cudaStreamWaitEvent(g_sB, g_evG0, 0);
    long long spmm_threads = (long long)M * 32;
    unsigned spmm_blocks = (unsigned)((spmm_threads + 255) / 256);
    spmm_half_kernel<<<spmm_blocks, 256, 0, g_sB>>>(out, M, 0);
    cudaEventRecord(g_evS0, g_sB);

    // stream 0: spmm half 1 (needs gemm1 + scatter), then join
    cudaStreamWaitEvent(0, g_evScat, 0);
    spmm_half_kernel<<<spmm_blocks, 256>>>(out, M, 128);
    cudaStreamWaitEvent(0, g_evS0, 0);
}

// round 15
// speedup vs baseline: 3.4608x; 1.0254x over previous
#include <cuda_runtime.h>
#include <cuda_fp16.h>
#include <cuda_bf16.h>
#include <cstdint>

#define MAXN 100000
#define MAXE 3200000
#define IN_DIM 512
#define OUT_DIM 256

// ---------------- scratch (static __device__, no runtime allocation) ----------------
__device__ __half g_xh[(size_t)MAXN * IN_DIM];           // x in fp16, 102.4 MB
__device__ __half g_support_h[(size_t)MAXN * OUT_DIM];   // tanh(x@W) in fp16, 51.2 MB
__device__ __half g_wT[(size_t)OUT_DIM * IN_DIM];        // W^T fp16 [256][512]
__device__ int   g_count[MAXN];
__device__ int   g_rowstart[MAXN + 1];
__device__ int   g_cursor[MAXN];
__device__ int2  g_edge[MAXE];          // packed (col, val-bits)
__device__ int   g_blocksum[128];
__device__ int   g_blockoff[128];

// ======================= helpers =======================
__device__ __forceinline__ uint32_t smem_u32(const void* p) {
    uint32_t a;
    asm("{ .reg .u64 t; cvta.to.shared.u64 t, %1; cvt.u32.u64 %0, t; }" : "=r"(a) : "l"(p));
    return a;
}

__device__ __forceinline__ void ldmx4(uint32_t& r0, uint32_t& r1, uint32_t& r2, uint32_t& r3,
                                      uint32_t addr) {
    asm volatile("ldmatrix.sync.aligned.m8n8.x4.shared.b16 {%0,%1,%2,%3}, [%4];"
                 : "=r"(r0), "=r"(r1), "=r"(r2), "=r"(r3) : "r"(addr));
}

__device__ __forceinline__ void mma_f16(float* c, const uint32_t* a, const uint32_t* b) {
    asm volatile(
        "mma.sync.aligned.m16n8k16.row.col.f32.f16.f16.f32 "
        "{%0,%1,%2,%3}, {%4,%5,%6,%7}, {%8,%9}, {%0,%1,%2,%3};"
        : "+f"(c[0]), "+f"(c[1]), "+f"(c[2]), "+f"(c[3])
        : "r"(a[0]), "r"(a[1]), "r"(a[2]), "r"(a[3]), "r"(b[0]), "r"(b[1]));
}

__device__ __forceinline__ void cpa16(uint32_t dst, const void* src, int nbytes) {
    asm volatile("cp.async.cg.shared.global [%0], [%1], 16, %2;"
                 :: "r"(dst), "l"(src), "r"(nbytes));
}
#define CPA_COMMIT() asm volatile("cp.async.commit_group;" ::: "memory")
#define CPA_WAIT(n)  asm volatile("cp.async.wait_group %0;" :: "n"(n) : "memory")

// ======================= x -> fp16 (one pass; keep in L2 for gemm) =======================
__global__ void convx_kernel(const float* __restrict__ x, long long total8) {
    long long i = (long long)blockIdx.x * blockDim.x + threadIdx.x;   // 8 floats per thread
    if (i >= total8) return;
    const float4* src = (const float4*)x + i * 2;
    float4 v0 = __ldcs(src);
    float4 v1 = __ldcs(src + 1);
    __half2 h0 = __floats2half2_rn(v0.x, v0.y);
    __half2 h1 = __floats2half2_rn(v0.z, v0.w);
    __half2 h2 = __floats2half2_rn(v1.x, v1.y);
    __half2 h3 = __floats2half2_rn(v1.z, v1.w);
    uint4 o = make_uint4(*(uint32_t*)&h0, *(uint32_t*)&h1, *(uint32_t*)&h2, *(uint32_t*)&h3);
    *((uint4*)g_xh + i) = o;
}

// ======================= W transpose -> fp16 =======================
__global__ void convw_kernel(const float* __restrict__ w) {
    int idx = blockIdx.x * blockDim.x + threadIdx.x;   // over 512*256
    if (idx >= IN_DIM * OUT_DIM) return;
    int k = idx / OUT_DIM, n = idx % OUT_DIM;
    g_wT[(size_t)n * IN_DIM + k] = __float2half_rn(w[idx]);
}

// ======================= fp16 HMMA GEMM, cp.async double-buffered, WIDE =======================
// grid = (M/128, 2): blockIdx.y selects the N half. All CTAs co-resident ->
// both halves' A reads dedup in L2 and tensor pipes fill.
#define GBK 64
#define GSTRIDE 72
#define NCHUNK (IN_DIM / GBK)   // 8
#define TILE_B 18432            // 128 * 72 * 2 bytes
#define GSMEM_TOTAL (4 * TILE_B)

__global__ __launch_bounds__(256, 2)
void gemm_mma_kernel(const int* __restrict__ act_ptr, int M)
{
    extern __shared__ __align__(16) char smem[];
    const uint32_t smem_b = smem_u32(smem);

    const int tid = threadIdx.x;
    const int lane = tid & 31, wid = tid >> 5;
    const int bm = blockIdx.x * 128;
    const int bn = blockIdx.y * 128;
    const int wm = (wid & 3) * 32;    // warp M offset
    const int wn = (wid >> 2) * 64;   // warp N offset

    float acc[2][8][4];
    #pragma unroll
    for (int i = 0; i < 2; i++)
        #pragma unroll
        for (int j = 0; j < 8; j++)
            #pragma unroll
            for (int q = 0; q < 4; q++) acc[i][j][q] = 0.f;

    const int ld_row = tid >> 3;     // 0..31, rows step by 32
    const int ld_seg = tid & 7;      // 0..7
    const int a_row = (lane & 15), a_koff = (lane >> 4) * 8;
    const int b_row = (lane & 7) + ((lane >> 4) & 1) * 8, b_koff = ((lane >> 3) & 1) * 8;

    auto load_stage = [&](int chunk, int stage) {
        const int kk = chunk * GBK;
        const uint32_t aB = smem_b + stage * 2 * TILE_B;
        const uint32_t bB = aB + TILE_B;
        #pragma unroll
        for (int it = 0; it < 4; it++) {
            int row = ld_row + it * 32;
            int grow = bm + row;
            int ok = (grow < M);
            const __half* src = g_xh + (size_t)(ok ? grow : 0) * IN_DIM + kk + ld_seg * 8;
            cpa16(aB + (uint32_t)(row * GSTRIDE + ld_seg * 8) * 2u, src, ok ? 16 : 0);
        }
        #pragma unroll
        for (int it = 0; it < 4; it++) {
            int i = tid + it * 256;
            int row = i >> 3, seg = i & 7;
            const __half* src = g_wT + (size_t)(bn + row) * IN_DIM + kk + seg * 8;
            cpa16(bB + (uint32_t)(row * GSTRIDE + seg * 8) * 2u, src, 16);
        }
        CPA_COMMIT();
    };

    load_stage(0, 0);

    for (int chunk = 0; chunk < NCHUNK; chunk++) {
        if (chunk + 1 < NCHUNK) {
            load_stage(chunk + 1, (chunk + 1) & 1);
            CPA_WAIT(1);
        } else {
            CPA_WAIT(0);
        }
        __syncthreads();

        const uint32_t sA_b = smem_b + (chunk & 1) * 2 * TILE_B;
        const uint32_t sB_b = sA_b + TILE_B;

        #pragma unroll
        for (int ks = 0; ks < 4; ks++) {
            const int k0 = ks * 16;
            uint32_t ah[2][4];
            #pragma unroll
            for (int mt = 0; mt < 2; mt++) {
                uint32_t eoff = (uint32_t)((wm + mt * 16 + a_row) * GSTRIDE + k0 + a_koff) * 2u;
                ldmx4(ah[mt][0], ah[mt][1], ah[mt][2], ah[mt][3], sA_b + eoff);
            }
            #pragma unroll
            for (int nt2 = 0; nt2 < 4; nt2++) {
                uint32_t eoff = (uint32_t)((wn + nt2 * 16 + b_row) * GSTRIDE + k0 + b_koff) * 2u;
                uint32_t bh[4];
                ldmx4(bh[0], bh[1], bh[2], bh[3], sB_b + eoff);
                #pragma unroll
                for (int mt = 0; mt < 2; mt++) {
                    #pragma unroll
                    for (int j = 0; j < 2; j++)
                        mma_f16(acc[mt][nt2 * 2 + j], ah[mt], &bh[j * 2]);
                }
            }
        }
        __syncthreads();
    }

    // ---- epilogue: tanh -> fp16 (default policy: keep support resident in L2) ----
    const int act = act_ptr ? act_ptr[0] : 1;
    #pragma unroll
    for (int mt = 0; mt < 2; mt++) {
        int r0 = bm + wm + mt * 16 + (lane >> 2);
        #pragma unroll
        for (int nt = 0; nt < 8; nt++) {
            int col = bn + wn + nt * 8 + (lane & 3) * 2;
            float c0 = acc[mt][nt][0], c1 = acc[mt][nt][1];
            float c2 = acc[mt][nt][2], c3 = acc[mt][nt][3];
            if (act) { c0 = tanhf(c0); c1 = tanhf(c1); c2 = tanhf(c2); c3 = tanhf(c3); }
            if (r0 < M)
                *(__half2*)(g_support_h + (size_t)r0 * OUT_DIM + col) = __floats2half2_rn(c0, c1);
            if (r0 + 8 < M)
                *(__half2*)(g_support_h + (size_t)(r0 + 8) * OUT_DIM + col) = __floats2half2_rn(c2, c3);
        }
    }
}

// ======================= CSR build =======================
__global__ void zero_counts(int N) {
    int i = blockIdx.x * blockDim.x + threadIdx.x;
    if (i < N) g_count[i] = 0;
}

__global__ void hist_kernel(const int* __restrict__ rows, int E) {
    int i4 = (blockIdx.x * blockDim.x + threadIdx.x) * 4;
    if (i4 + 3 < E) {
        int4 r = __ldcs((const int4*)(rows + i4));
        atomicAdd(&g_count[r.x], 1);
        atomicAdd(&g_count[r.y], 1);
        atomicAdd(&g_count[r.z], 1);
        atomicAdd(&g_count[r.w], 1);
    } else {
        for (int j = i4; j < E; j++) atomicAdd(&g_count[rows[j]], 1);
    }
}

// -- parallel scan, 3 phases, 1024 counts per block --
__global__ __launch_bounds__(1024) void scan_phase1(int N) {
    __shared__ int ws[32];
    int b = blockIdx.x, tid = threadIdx.x, lane = tid & 31, wid = tid >> 5;
    int i = b * 1024 + tid;
    int v = (i < N) ? g_count[i] : 0;
    #pragma unroll
    for (int o = 16; o > 0; o >>= 1) v += __shfl_down_sync(0xFFFFFFFFu, v, o);
    if (lane == 0) ws[wid] = v;
    __syncthreads();
    if (wid == 0) {
        int s = ws[lane];
        #pragma unroll
        for (int o = 16; o > 0; o >>= 1) s += __shfl_down_sync(0xFFFFFFFFu, s, o);
        if (lane == 0) g_blocksum[b] = s;
    }
}

__global__ __launch_bounds__(128) void scan_phase2(int NB) {
    __shared__ int ws[4];
    int tid = threadIdx.x, lane = tid & 31, wid = tid >> 5;
    int v = (tid < NB) ? g_blocksum[tid] : 0;
    int xv = v;
    #pragma unroll
    for (int o = 1; o < 32; o <<= 1) {
        int t = __shfl_up_sync(0xFFFFFFFFu, xv, o);
        if (lane >= o) xv += t;
    }
    if (lane == 31) ws[wid] = xv;
    __syncthreads();
    int carry = 0;
    #pragma unroll
    for (int w = 0; w < 4; w++) { if (w < wid) carry += ws[w]; }
    if (tid < NB) g_blockoff[tid] = carry + xv - v;   // exclusive
}

__global__ __launch_bounds__(1024) void scan_phase3(int N, int E) {
    __shared__ int ws[32];
    int b = blockIdx.x, tid = threadIdx.x, lane = tid & 31, wid = tid >> 5;
    int i = b * 1024 + tid;
    int v = (i < N) ? g_count[i] : 0;
    int xv = v;
    #pragma unroll
    for (int o = 1; o < 32; o <<= 1) {
        int t = __shfl_up_sync(0xFFFFFFFFu, xv, o);
        if (lane >= o) xv += t;
    }
    if (lane == 31) ws[wid] = xv;
    __syncthreads();
    if (wid == 0) {
        int wv = ws[lane];
        int y = wv;
        #pragma unroll
        for (int o = 1; o < 32; o <<= 1) {
            int t = __shfl_up_sync(0xFFFFFFFFu, y, o);
            if (lane >= o) y += t;
        }
        ws[lane] = y - wv;   // exclusive warp offsets
    }
    __syncthreads();
    int off = g_blockoff[b] + ws[wid] + xv - v;   // global exclusive prefix
    if (i < N) { g_rowstart[i] = off; g_cursor[i] = off; }
    if (i == N - 1) g_rowstart[N] = off + v;      // == E
}

__global__ void scatter_kernel(const int* __restrict__ rows,
                               const int* __restrict__ cols,
                               const float* __restrict__ vals, int E) {
    int i4 = (blockIdx.x * blockDim.x + threadIdx.x) * 4;
    if (i4 + 3 < E) {
        int4   r = __ldcs((const int4*)(rows + i4));
        int4   c = __ldcs((const int4*)(cols + i4));
        float4 v = __ldcs((const float4*)(vals + i4));
        int p0 = atomicAdd(&g_cursor[r.x], 1);
        g_edge[p0] = make_int2(c.x, __float_as_int(v.x));
        int p1 = atomicAdd(&g_cursor[r.y], 1);
        g_edge[p1] = make_int2(c.y, __float_as_int(v.y));
        int p2 = atomicAdd(&g_cursor[r.z], 1);
        g_edge[p2] = make_int2(c.z, __float_as_int(v.z));
        int p3 = atomicAdd(&g_cursor[r.w], 1);
        g_edge[p3] = make_int2(c.w, __float_as_int(v.w));
    } else {
        for (int j = i4; j < E; j++) {
            int p = atomicAdd(&g_cursor[rows[j]], 1);
            g_edge[p] = make_int2(cols[j], __float_as_int(vals[j]));
        }
    }
}

// ======================= SpMM WIDE: grid.y=2 column halves, warp per row, MLP=8 =======================
__global__ __launch_bounds__(256)
void spmm_kernel(float* __restrict__ out, int N) {
    int wrow = (blockIdx.x * blockDim.x + threadIdx.x) >> 5;
    int lane = threadIdx.x & 31;
    if (wrow >= N) return;
    int s = g_rowstart[wrow];
    int e = g_rowstart[wrow + 1];
    float a0 = 0.f, a1 = 0.f, a2 = 0.f, a3 = 0.f;
    const size_t loff = (size_t)(blockIdx.y * 128) + lane * 4;
    int i = s;
    for (; i + 8 <= e; i += 8) {
        int2 ed[8];
        uint2 q[8];
        #pragma unroll
        for (int u = 0; u < 8; u++) ed[u] = g_edge[i + u];
        #pragma unroll
        for (int u = 0; u < 8; u++)
            q[u] = *(const uint2*)(g_support_h + (size_t)ed[u].x * OUT_DIM + loff);
        #pragma unroll
        for (int u = 0; u < 8; u++) {
            float v = __int_as_float(ed[u].y);
            float2 f0 = __half22float2(*(const __half2*)&q[u].x);
            float2 f1 = __half22float2(*(const __half2*)&q[u].y);
            a0 += v * f0.x; a1 += v * f0.y; a2 += v * f1.x; a3 += v * f1.y;
        }
    }
    for (; i < e; i++) {
        int2 ed = g_edge[i];
        float v = __int_as_float(ed.y);
        uint2 q = *(const uint2*)(g_support_h + (size_t)ed.x * OUT_DIM + loff);
        float2 f0 = __half22float2(*(const __half2*)&q.x);
        float2 f1 = __half22float2(*(const __half2*)&q.y);
        a0 += v * f0.x; a1 += v * f0.y; a2 += v * f1.x; a3 += v * f1.y;
    }
    __stcs((float4*)(out + (size_t)wrow * OUT_DIM + loff), make_float4(a0, a1, a2, a3));
}

// ---------------- host-side stream/event objects + func attrs (at load, before capture) ----------------
static cudaStream_t g_sB;
static cudaEvent_t  g_evFork, g_evScat;
struct _InitStreams {
    _InitStreams() {
        cudaStreamCreate(&g_sB);
        cudaEventCreateWithFlags(&g_evFork, cudaEventDisableTiming);
        cudaEventCreateWithFlags(&g_evScat, cudaEventDisableTiming);
        cudaFuncSetAttribute(gemm_mma_kernel,
                             cudaFuncAttributeMaxDynamicSharedMemorySize, GSMEM_TOTAL);
    }
};
static _InitStreams g_init_streams;

// ======================= launch =======================
extern "C" void kernel_launch(void* const* d_in, const int* in_sizes, int n_in,
                              void* d_out, int out_size) {
    const float* x    = (const float*)d_in[0];
    const float* w    = (const float*)d_in[1];
    const int*   erow = (const int*)d_in[2];
    const int*   ecol = (const int*)d_in[3];
    const float* eval = (const float*)d_in[4];
    const int*   act  = (n_in > 5) ? (const int*)d_in[5] : nullptr;

    int M = in_sizes[0] / IN_DIM;   // 100000
    int E = in_sizes[2];            // 3200000
    float* out = (float*)d_out;

    // ---- fork: CSR chain on sB ----
    cudaEventRecord(g_evFork, 0);
    cudaStreamWaitEvent(g_sB, g_evFork, 0);

    zero_counts<<<(M + 255) / 256, 256, 0, g_sB>>>(M);
    hist_kernel<<<(E / 4 + 255) / 256, 256, 0, g_sB>>>(erow, E);
    int NB = (M + 1023) / 1024;     // 98
    scan_phase1<<<NB, 1024, 0, g_sB>>>(M);
    scan_phase2<<<1, 128, 0, g_sB>>>(NB);
    scan_phase3<<<NB, 1024, 0, g_sB>>>(M, E);
    scatter_kernel<<<(E / 4 + 255) / 256, 256, 0, g_sB>>>(erow, ecol, eval, E);
    cudaEventRecord(g_evScat, g_sB);

    // ---- stream 0: convw -> convx -> wide gemm (both N halves co-resident) ----
    convw_kernel<<<(IN_DIM * OUT_DIM + 255) / 256, 256>>>(w);
    long long total8 = (long long)M * IN_DIM / 8;
    convx_kernel<<<(unsigned)((total8 + 255) / 256), 256>>>(x, total8);
    int gtiles = (M + 127) / 128;
    dim3 ggrid(gtiles, 2);
    gemm_mma_kernel<<<ggrid, 256, GSMEM_TOTAL>>>(act, M);

    // ---- join, then wide spmm (both column halves co-resident) ----
    cudaStreamWaitEvent(0, g_evScat, 0);
    long long spmm_threads = (long long)M * 32;
    dim3 sgrid((unsigned)((spmm_threads + 255) / 256), 2);
    spmm_kernel<<<sgrid, 256>>>(out, M);
}